// round 1
// baseline (speedup 1.0000x reference)
#include <cuda_runtime.h>

// Problem constants (fixed by the dataset)
#define NROWS  4096
#define DMODEL 512
#define NHEAD  8
#define DK     64

// Scratch (device globals — allocation-free per harness rules)
__device__ float g_q[NROWS * DMODEL];
__device__ float g_k[NROWS * DMODEL];
__device__ float g_v[NROWS * DMODEL];
__device__ float g_y[NROWS * DMODEL];

// ---------------------------------------------------------------------------
// SGEMM with bias: C[M,N] = A[M,K] @ B[K,N] + bias[N]
// 128x128 block tile, BK=16, 256 threads, 8x8 per-thread micro-tile.
// ---------------------------------------------------------------------------
#define BM 128
#define BN 128
#define BK 16
#define TM 8
#define TN 8

__global__ __launch_bounds__(256, 1)
void sgemm_bias(const float* __restrict__ A, const float* __restrict__ B,
                const float* __restrict__ bias, float* __restrict__ C,
                int M, int N, int K)
{
    __shared__ float As[BK][BM];   // A tile stored transposed: As[k][m]
    __shared__ float Bs[BK][BN];

    const int tid = threadIdx.x;
    const int bm  = blockIdx.y * BM;
    const int bn  = blockIdx.x * BN;

    // Global-load mapping
    const int arow = tid >> 2;           // 0..63 (and +64 for second load)
    const int acol = (tid & 3) << 2;     // 0,4,8,12
    const int brow = tid >> 5;           // 0..7  (and +8)
    const int bcol = (tid & 31) << 2;    // 0..124

    // Compute mapping: 16x16 thread grid, each 8x8 outputs
    const int trow = (tid >> 4) * TM;
    const int tcol = (tid & 15) * TN;

    float acc[TM][TN];
    #pragma unroll
    for (int i = 0; i < TM; i++)
        #pragma unroll
        for (int j = 0; j < TN; j++)
            acc[i][j] = 0.f;

    const float* Aptr = A + (size_t)(bm + arow) * K + acol;
    const float* Bptr = B + (size_t)brow * N + bn + bcol;

    for (int k0 = 0; k0 < K; k0 += BK) {
        float4 a0 = *(const float4*)(Aptr + k0);
        float4 a1 = *(const float4*)(Aptr + (size_t)64 * K + k0);
        float4 b0 = *(const float4*)(Bptr + (size_t)k0 * N);
        float4 b1 = *(const float4*)(Bptr + (size_t)(k0 + 8) * N);

        As[acol + 0][arow] = a0.x;
        As[acol + 1][arow] = a0.y;
        As[acol + 2][arow] = a0.z;
        As[acol + 3][arow] = a0.w;
        As[acol + 0][arow + 64] = a1.x;
        As[acol + 1][arow + 64] = a1.y;
        As[acol + 2][arow + 64] = a1.z;
        As[acol + 3][arow + 64] = a1.w;
        *(float4*)&Bs[brow][bcol]     = b0;
        *(float4*)&Bs[brow + 8][bcol] = b1;
        __syncthreads();

        #pragma unroll
        for (int kk = 0; kk < BK; kk++) {
            float a[TM], b[TN];
            *(float4*)&a[0] = *(const float4*)&As[kk][trow];
            *(float4*)&a[4] = *(const float4*)&As[kk][trow + 4];
            *(float4*)&b[0] = *(const float4*)&Bs[kk][tcol];
            *(float4*)&b[4] = *(const float4*)&Bs[kk][tcol + 4];
            #pragma unroll
            for (int i = 0; i < TM; i++)
                #pragma unroll
                for (int j = 0; j < TN; j++)
                    acc[i][j] = fmaf(a[i], b[j], acc[i][j]);
        }
        __syncthreads();
    }

    #pragma unroll
    for (int i = 0; i < TM; i++) {
        float* Cp = C + (size_t)(bm + trow + i) * N + bn + tcol;
        #pragma unroll
        for (int j = 0; j < TN; j++)
            Cp[j] = acc[i][j] + bias[bn + tcol + j];
    }
}

// ---------------------------------------------------------------------------
// Channel-wise outer-product attention, fused with the (x_q - attn) epilogue.
// One warp per (n, h). Lane L handles channels i = L and i = L+32.
//   out_i = sum_j exp(q_i * k_j / 8) * v_j / sum_j exp(q_i * k_j / 8)
// No max-subtraction needed: |q_i*k_j/8| <~ 4, exp is safe in fp32 and the
// softmax ratio is identical to the max-shifted form.
// ---------------------------------------------------------------------------
__global__ __launch_bounds__(256, 8)
void attn_residual_kernel(const float* __restrict__ q, const float* __restrict__ k,
                          const float* __restrict__ v, const float* __restrict__ xq,
                          float* __restrict__ y)
{
    __shared__ float sk[8][DK];
    __shared__ float sv[8][DK];

    const int warp = threadIdx.x >> 5;
    const int lane = threadIdx.x & 31;
    const int gw   = blockIdx.x * 8 + warp;   // flat (n*H + h)
    const int base = (gw >> 3) * DMODEL + (gw & 7) * DK;

    sk[warp][lane]      = k[base + lane];
    sk[warp][lane + 32] = k[base + lane + 32];
    sv[warp][lane]      = v[base + lane];
    sv[warp][lane + 32] = v[base + lane + 32];
    const float a0 = q[base + lane]      * 0.125f;
    const float a1 = q[base + lane + 32] * 0.125f;
    __syncwarp();

    float num0 = 0.f, den0 = 0.f, num1 = 0.f, den1 = 0.f;
    #pragma unroll 8
    for (int j = 0; j < DK; j++) {
        const float kj = sk[warp][j];
        const float vj = sv[warp][j];
        const float e0 = __expf(a0 * kj);
        const float e1 = __expf(a1 * kj);
        num0 = fmaf(e0, vj, num0);
        den0 += e0;
        num1 = fmaf(e1, vj, num1);
        den1 += e1;
    }
    y[base + lane]      = xq[base + lane]      - num0 / den0;
    y[base + lane + 32] = xq[base + lane + 32] - num1 / den1;
}

// ---------------------------------------------------------------------------
// Launch: 3 projection GEMMs -> fused attention/residual -> output GEMM
// ---------------------------------------------------------------------------
extern "C" void kernel_launch(void* const* d_in, const int* in_sizes, int n_in,
                              void* d_out, int out_size)
{
    const float* x_q = (const float*)d_in[0];
    const float* x_k = (const float*)d_in[1];
    const float* x_v = (const float*)d_in[2];
    const float* Wq  = (const float*)d_in[3];
    const float* bq  = (const float*)d_in[4];
    const float* Wk  = (const float*)d_in[5];
    const float* bk  = (const float*)d_in[6];
    const float* Wv  = (const float*)d_in[7];
    const float* bv  = (const float*)d_in[8];
    const float* Wo  = (const float*)d_in[9];
    const float* bo  = (const float*)d_in[10];
    float* out = (float*)d_out;

    float *gq, *gk, *gv, *gy;
    cudaGetSymbolAddress((void**)&gq, g_q);
    cudaGetSymbolAddress((void**)&gk, g_k);
    cudaGetSymbolAddress((void**)&gv, g_v);
    cudaGetSymbolAddress((void**)&gy, g_y);

    dim3 gblock(256);
    dim3 ggrid(DMODEL / BN, NROWS / BM);   // (4, 32)

    sgemm_bias<<<ggrid, gblock>>>(x_q, Wq, bq, gq, NROWS, DMODEL, DMODEL);
    sgemm_bias<<<ggrid, gblock>>>(x_k, Wk, bk, gk, NROWS, DMODEL, DMODEL);
    sgemm_bias<<<ggrid, gblock>>>(x_v, Wv, bv, gv, NROWS, DMODEL, DMODEL);

    attn_residual_kernel<<<NROWS * NHEAD / 8, 256>>>(gq, gk, gv, x_q, gy);

    sgemm_bias<<<ggrid, gblock>>>(gy, Wo, bo, out, NROWS, DMODEL, DMODEL);
}

// round 3
// speedup vs baseline: 2.2832x; 2.2832x over previous
#include <cuda_runtime.h>
#include <cuda_bf16.h>
#include <cstdint>

#define NROWS  4096
#define DMODEL 512
#define DK     64

// ---------------- scratch (device globals; allocation-free) -----------------
__device__ float g_q[NROWS * DMODEL];
__device__ float g_k[NROWS * DMODEL];
__device__ float g_v[NROWS * DMODEL];
__device__ __nv_bfloat16 g_ah[NROWS * DMODEL];
__device__ __nv_bfloat16 g_al[NROWS * DMODEL];
__device__ __nv_bfloat16 g_wth[4][DMODEL * DMODEL];
__device__ __nv_bfloat16 g_wtl[4][DMODEL * DMODEL];
__device__ __nv_bfloat16 g_yh[NROWS * DMODEL];
__device__ __nv_bfloat16 g_yl[NROWS * DMODEL];

// ---------------- PTX helpers ----------------
static __device__ __forceinline__ uint32_t s2u(const void* p) {
    uint32_t a;
    asm("{ .reg .u64 t; cvta.to.shared.u64 t, %1; cvt.u32.u64 %0, t; }" : "=r"(a) : "l"(p));
    return a;
}
static __device__ __forceinline__ void cp16(uint32_t s, const void* g) {
    asm volatile("cp.async.cg.shared.global [%0], [%1], 16;" :: "r"(s), "l"(g));
}
static __device__ __forceinline__ void ldsm4(uint32_t& r0, uint32_t& r1, uint32_t& r2,
                                             uint32_t& r3, uint32_t a) {
    asm volatile("ldmatrix.sync.aligned.m8n8.x4.shared.b16 {%0,%1,%2,%3}, [%4];"
                 : "=r"(r0), "=r"(r1), "=r"(r2), "=r"(r3) : "r"(a));
}
static __device__ __forceinline__ void ldsm2(uint32_t& r0, uint32_t& r1, uint32_t a) {
    asm volatile("ldmatrix.sync.aligned.m8n8.x2.shared.b16 {%0,%1}, [%2];"
                 : "=r"(r0), "=r"(r1) : "r"(a));
}
static __device__ __forceinline__ void mma_bf16(float* c, const uint32_t* a, const uint32_t* b) {
    asm volatile(
        "mma.sync.aligned.m16n8k16.row.col.f32.bf16.bf16.f32 "
        "{%0,%1,%2,%3}, {%4,%5,%6,%7}, {%8,%9}, {%0,%1,%2,%3};"
        : "+f"(c[0]), "+f"(c[1]), "+f"(c[2]), "+f"(c[3])
        : "r"(a[0]), "r"(a[1]), "r"(a[2]), "r"(a[3]), "r"(b[0]), "r"(b[1]));
}
#define SWZ(x) ((x) ^ (((x) >> 3) & 0x70))

// ---------------- GEMM: C[4096,512] = (Ah+Al) @ (Bh+Bl)^T + bias -------------
// A splits: [M,K] bf16 row-major. B splits: [N,K] bf16 row-major (pre-transposed).
// CTA tile 128x128, 256 threads (8 warps, warp tile 64x32), K chunks of 64,
// 3-stage cp.async pipeline. bf16x3: C = Ah*Bh + Ah*Bl + Al*Bh (fp32 accum).
#define KCHUNKS 8
#define STAGE_BYTES 65536     // Ah(16K) | Al(16K) | Bh(16K) | Bl(16K), rows of 128B
#define GSMEM_TOTAL (3 * STAGE_BYTES)

__global__ __launch_bounds__(256, 1)
void gemm_mma_bf16x3(const __nv_bfloat16* __restrict__ Ah, const __nv_bfloat16* __restrict__ Al,
                     const __nv_bfloat16* __restrict__ Bh, const __nv_bfloat16* __restrict__ Bl,
                     const float* __restrict__ bias, float* __restrict__ C)
{
    extern __shared__ char smem[];
    const uint32_t sb = s2u(smem);
    const int tid = threadIdx.x, wid = tid >> 5, lane = tid & 31;
    const int m0 = blockIdx.y << 7, n0 = blockIdx.x << 7;
    const int wm = wid & 1, wn = wid >> 1;          // warp tile: (wm*64, wn*32)

    // per-thread global-load mapping: 4 (row,chunk16B) slots per tensor
    // slot idx = i*256+tid ; row = idx>>3 (0..127), c16 = idx&7
    // ldmatrix per-thread source rows:
    const int a_row  = (wm << 6) + (((lane >> 3) & 1) << 3) + (lane & 7); // + mi*16
    const int a_kh   = lane >> 4;                                          // k half
    const int b_row  = (wn << 5) + (lane & 7);                             // + ni*8
    const int b_kh   = (lane >> 3) & 1;

    float acc[4][4][4];
    #pragma unroll
    for (int i = 0; i < 4; i++)
        #pragma unroll
        for (int j = 0; j < 4; j++)
            #pragma unroll
            for (int r = 0; r < 4; r++) acc[i][j][r] = 0.f;

    auto load_stage = [&](int chunk, int st) {
        const uint32_t base = sb + st * STAGE_BYTES;
        const int k0 = chunk << 6;
        #pragma unroll
        for (int i = 0; i < 4; i++) {
            const int idx = (i << 8) + tid;
            const int row = idx >> 3, c = idx & 7;
            const uint32_t so = SWZ((row << 7) + (c << 4));
            const size_t aoff = (((size_t)(m0 + row) << 9) + k0 + (c << 3)) * 2;
            const size_t boff = (((size_t)(n0 + row) << 9) + k0 + (c << 3)) * 2;
            cp16(base +         so, (const char*)Ah + aoff);
            cp16(base + 16384 + so, (const char*)Al + aoff);
            cp16(base + 32768 + so, (const char*)Bh + boff);
            cp16(base + 49152 + so, (const char*)Bl + boff);
        }
    };

    load_stage(0, 0);
    asm volatile("cp.async.commit_group;" ::: "memory");
    load_stage(1, 1);
    asm volatile("cp.async.commit_group;" ::: "memory");

    for (int c = 0; c < KCHUNKS; c++) {
        if (c < KCHUNKS - 1)
            asm volatile("cp.async.wait_group 1;" ::: "memory");
        else
            asm volatile("cp.async.wait_group 0;" ::: "memory");
        __syncthreads();

        if (c + 2 < KCHUNKS) {
            load_stage(c + 2, (c + 2) % 3);
            asm volatile("cp.async.commit_group;" ::: "memory");
        }

        const uint32_t stb = sb + (c % 3) * STAGE_BYTES;
        #pragma unroll
        for (int t = 0; t < 4; t++) {
            uint32_t ah[4][4], al2[4][4], bh[4][2], bl[4][2];
            // A-hi fragments: ldmatrix.x4 per 16-row tile
            #pragma unroll
            for (int mi = 0; mi < 4; mi++) {
                const int row = a_row + (mi << 4);
                const uint32_t so = SWZ((row << 7) + (((t << 1) + a_kh) << 4));
                ldsm4(ah[mi][0], ah[mi][1], ah[mi][2], ah[mi][3], stb + so);
            }
            // B-hi fragments
            #pragma unroll
            for (int ni = 0; ni < 4; ni++) {
                const int row = b_row + (ni << 3);
                const uint32_t so = SWZ((row << 7) + (((t << 1) + b_kh) << 4));
                ldsm2(bh[ni][0], bh[ni][1], stb + 32768 + so);
            }
            #pragma unroll
            for (int mi = 0; mi < 4; mi++)
                #pragma unroll
                for (int ni = 0; ni < 4; ni++)
                    mma_bf16(acc[mi][ni], ah[mi], bh[ni]);
            // B-lo
            #pragma unroll
            for (int ni = 0; ni < 4; ni++) {
                const int row = b_row + (ni << 3);
                const uint32_t so = SWZ((row << 7) + (((t << 1) + b_kh) << 4));
                ldsm2(bl[ni][0], bl[ni][1], stb + 49152 + so);
            }
            #pragma unroll
            for (int mi = 0; mi < 4; mi++)
                #pragma unroll
                for (int ni = 0; ni < 4; ni++)
                    mma_bf16(acc[mi][ni], ah[mi], bl[ni]);
            // A-lo
            #pragma unroll
            for (int mi = 0; mi < 4; mi++) {
                const int row = a_row + (mi << 4);
                const uint32_t so = SWZ((row << 7) + (((t << 1) + a_kh) << 4));
                ldsm4(al2[mi][0], al2[mi][1], al2[mi][2], al2[mi][3], stb + 16384 + so);
            }
            #pragma unroll
            for (int mi = 0; mi < 4; mi++)
                #pragma unroll
                for (int ni = 0; ni < 4; ni++)
                    mma_bf16(acc[mi][ni], al2[mi], bh[ni]);
        }
        __syncthreads();
    }

    // epilogue: c-fragment layout -> global, + bias
    #pragma unroll
    for (int mi = 0; mi < 4; mi++) {
        const int row = m0 + (wm << 6) + (mi << 4) + (lane >> 2);
        #pragma unroll
        for (int ni = 0; ni < 4; ni++) {
            const int col = n0 + (wn << 5) + (ni << 3) + ((lane & 3) << 1);
            const float b0 = __ldg(bias + col), b1 = __ldg(bias + col + 1);
            float2 o0 = {acc[mi][ni][0] + b0, acc[mi][ni][1] + b1};
            float2 o1 = {acc[mi][ni][2] + b0, acc[mi][ni][3] + b1};
            *(float2*)(C + (size_t)row * DMODEL + col)       = o0;
            *(float2*)(C + (size_t)(row + 8) * DMODEL + col) = o1;
        }
    }
}

// ---------------- helpers: splits & weight transpose+split ------------------
__global__ void split_bf16(const float* __restrict__ X,
                           __nv_bfloat16* __restrict__ H, __nv_bfloat16* __restrict__ L)
{
    const int i = blockIdx.x * 256 + threadIdx.x;
    const float v = X[i];
    const __nv_bfloat16 h = __float2bfloat16(v);
    H[i] = h;
    L[i] = __float2bfloat16(v - __bfloat162float(h));
}

__global__ void transpose_split(const float* __restrict__ W,
                                __nv_bfloat16* __restrict__ Th, __nv_bfloat16* __restrict__ Tl)
{
    __shared__ float t[32][33];
    const int bx = blockIdx.x * 32, by = blockIdx.y * 32;
    const int x = bx + threadIdx.x;
    #pragma unroll
    for (int j = 0; j < 32; j += 8)
        t[threadIdx.y + j][threadIdx.x] = W[(size_t)(by + threadIdx.y + j) * DMODEL + x];
    __syncthreads();
    const int ox = by + threadIdx.x;
    #pragma unroll
    for (int j = 0; j < 32; j += 8) {
        const float v = t[threadIdx.x][threadIdx.y + j];
        const __nv_bfloat16 h = __float2bfloat16(v);
        const size_t o = (size_t)(bx + threadIdx.y + j) * DMODEL + ox;
        Th[o] = h;
        Tl[o] = __float2bfloat16(v - __bfloat162float(h));
    }
}

// ---------------- fused channel-wise attention + residual + bf16 split ------
__global__ __launch_bounds__(256, 8)
void attn_residual_split(const float* __restrict__ q, const float* __restrict__ k,
                         const float* __restrict__ v, const float* __restrict__ xq,
                         __nv_bfloat16* __restrict__ yh, __nv_bfloat16* __restrict__ yl)
{
    __shared__ float sk[8][DK];
    __shared__ float sv[8][DK];
    const int warp = threadIdx.x >> 5;
    const int lane = threadIdx.x & 31;
    const int gw   = blockIdx.x * 8 + warp;
    const int base = (gw >> 3) * DMODEL + (gw & 7) * DK;

    sk[warp][lane]      = k[base + lane];
    sk[warp][lane + 32] = k[base + lane + 32];
    sv[warp][lane]      = v[base + lane];
    sv[warp][lane + 32] = v[base + lane + 32];
    const float a0 = q[base + lane]      * 0.125f;
    const float a1 = q[base + lane + 32] * 0.125f;
    __syncwarp();

    float num0 = 0.f, den0 = 0.f, num1 = 0.f, den1 = 0.f;
    #pragma unroll 8
    for (int j = 0; j < DK; j++) {
        const float kj = sk[warp][j];
        const float vj = sv[warp][j];
        const float e0 = __expf(a0 * kj);
        const float e1 = __expf(a1 * kj);
        num0 = fmaf(e0, vj, num0);
        den0 += e0;
        num1 = fmaf(e1, vj, num1);
        den1 += e1;
    }
    const float y0 = xq[base + lane]      - num0 / den0;
    const float y1 = xq[base + lane + 32] - num1 / den1;
    const __nv_bfloat16 h0 = __float2bfloat16(y0);
    const __nv_bfloat16 h1 = __float2bfloat16(y1);
    yh[base + lane]      = h0;
    yl[base + lane]      = __float2bfloat16(y0 - __bfloat162float(h0));
    yh[base + lane + 32] = h1;
    yl[base + lane + 32] = __float2bfloat16(y1 - __bfloat162float(h1));
}

// ---------------- launch ------------------------------------------------------
extern "C" void kernel_launch(void* const* d_in, const int* in_sizes, int n_in,
                              void* d_out, int out_size)
{
    const float* x_q = (const float*)d_in[0];
    const float* x_k = (const float*)d_in[1];
    const float* x_v = (const float*)d_in[2];
    const float* W[4] = {(const float*)d_in[3], (const float*)d_in[5],
                         (const float*)d_in[7], (const float*)d_in[9]};
    const float* bq = (const float*)d_in[4];
    const float* bk = (const float*)d_in[6];
    const float* bv = (const float*)d_in[8];
    const float* bo = (const float*)d_in[10];
    float* out = (float*)d_out;

    static int configured = 0;
    cudaFuncSetAttribute(gemm_mma_bf16x3, cudaFuncAttributeMaxDynamicSharedMemorySize,
                         GSMEM_TOTAL);
    (void)configured;

    float *gq, *gk, *gv;
    __nv_bfloat16 *ah, *al, *wth, *wtl, *yh, *yl;
    cudaGetSymbolAddress((void**)&gq, g_q);
    cudaGetSymbolAddress((void**)&gk, g_k);
    cudaGetSymbolAddress((void**)&gv, g_v);
    cudaGetSymbolAddress((void**)&ah, g_ah);
    cudaGetSymbolAddress((void**)&al, g_al);
    cudaGetSymbolAddress((void**)&wth, g_wth);
    cudaGetSymbolAddress((void**)&wtl, g_wtl);
    cudaGetSymbolAddress((void**)&yh, g_yh);
    cudaGetSymbolAddress((void**)&yl, g_yl);

    const dim3 tb(32, 8), tg(16, 16);
    for (int i = 0; i < 4; i++)
        transpose_split<<<tg, tb>>>(W[i], wth + (size_t)i * DMODEL * DMODEL,
                                          wtl + (size_t)i * DMODEL * DMODEL);

    const dim3 gg(DMODEL / 128, NROWS / 128);   // (4, 32)
    const int nsplit = NROWS * DMODEL / 256;

    split_bf16<<<nsplit, 256>>>(x_q, ah, al);
    gemm_mma_bf16x3<<<gg, 256, GSMEM_TOTAL>>>(ah, al, wth, wtl, bq, gq);

    split_bf16<<<nsplit, 256>>>(x_k, ah, al);
    gemm_mma_bf16x3<<<gg, 256, GSMEM_TOTAL>>>(ah, al, wth + (size_t)1 * DMODEL * DMODEL,
                                              wtl + (size_t)1 * DMODEL * DMODEL, bk, gk);

    split_bf16<<<nsplit, 256>>>(x_v, ah, al);
    gemm_mma_bf16x3<<<gg, 256, GSMEM_TOTAL>>>(ah, al, wth + (size_t)2 * DMODEL * DMODEL,
                                              wtl + (size_t)2 * DMODEL * DMODEL, bv, gv);

    attn_residual_split<<<NROWS, 256>>>(gq, gk, gv, x_q, yh, yl);

    gemm_mma_bf16x3<<<gg, 256, GSMEM_TOTAL>>>(yh, yl, wth + (size_t)3 * DMODEL * DMODEL,
                                              wtl + (size_t)3 * DMODEL * DMODEL, bo, out);
}

// round 4
// speedup vs baseline: 2.6690x; 1.1690x over previous
#include <cuda_runtime.h>
#include <cuda_bf16.h>
#include <cstdint>

#define NROWS  4096
#define DMODEL 512
#define DK     64
#define ND     (NROWS * DMODEL)
#define DD     (DMODEL * DMODEL)

// ---------------- scratch (device globals; allocation-free) -----------------
__device__ float g_q[ND];
__device__ float g_k[ND];
__device__ float g_v[ND];
__device__ __nv_bfloat16 g_xh[3][ND];
__device__ __nv_bfloat16 g_xl[3][ND];
__device__ __nv_bfloat16 g_wth[4][DD];
__device__ __nv_bfloat16 g_wtl[4][DD];
__device__ __nv_bfloat16 g_yh[ND];
__device__ __nv_bfloat16 g_yl[ND];

// ---------------- PTX helpers ----------------
static __device__ __forceinline__ uint32_t s2u(const void* p) {
    uint32_t a;
    asm("{ .reg .u64 t; cvta.to.shared.u64 t, %1; cvt.u32.u64 %0, t; }" : "=r"(a) : "l"(p));
    return a;
}
static __device__ __forceinline__ void cp16(uint32_t s, const void* g) {
    asm volatile("cp.async.cg.shared.global [%0], [%1], 16;" :: "r"(s), "l"(g));
}
static __device__ __forceinline__ void ldsm4(uint32_t& r0, uint32_t& r1, uint32_t& r2,
                                             uint32_t& r3, uint32_t a) {
    asm volatile("ldmatrix.sync.aligned.m8n8.x4.shared.b16 {%0,%1,%2,%3}, [%4];"
                 : "=r"(r0), "=r"(r1), "=r"(r2), "=r"(r3) : "r"(a));
}
static __device__ __forceinline__ void ldsm2(uint32_t& r0, uint32_t& r1, uint32_t a) {
    asm volatile("ldmatrix.sync.aligned.m8n8.x2.shared.b16 {%0,%1}, [%2];"
                 : "=r"(r0), "=r"(r1) : "r"(a));
}
static __device__ __forceinline__ void mma_bf16(float* c, const uint32_t* a, const uint32_t* b) {
    asm volatile(
        "mma.sync.aligned.m16n8k16.row.col.f32.bf16.bf16.f32 "
        "{%0,%1,%2,%3}, {%4,%5,%6,%7}, {%8,%9}, {%0,%1,%2,%3};"
        : "+f"(c[0]), "+f"(c[1]), "+f"(c[2]), "+f"(c[3])
        : "r"(a[0]), "r"(a[1]), "r"(a[2]), "r"(a[3]), "r"(b[0]), "r"(b[1]));
}
#define SWZ(x) ((x) ^ (((x) >> 3) & 0x70))

// ---------------- GEMM: C[4096,512] = (Ah+Al) @ (Bh+Bl)^T + bias -------------
// bf16x3: C = Ah*Bh + Ah*Bl + Al*Bh (fp32 accum). B pre-transposed [N,K] K-major.
// CTA tile 128x128, 256 threads (8 warps, warp tile 64x32), K chunks of 64,
// 3-stage cp.async pipeline. blockIdx.z selects the problem.
#define KCHUNKS 8
#define STAGE_BYTES 65536     // Ah(16K) | Al(16K) | Bh(16K) | Bl(16K), rows of 128B
#define GSMEM_TOTAL (3 * STAGE_BYTES)

struct GemmPtrs {
    const __nv_bfloat16* Ah[3];
    const __nv_bfloat16* Al[3];
    const __nv_bfloat16* Bh[3];
    const __nv_bfloat16* Bl[3];
    const float*         bias[3];
    float*               C[3];
};

__global__ __launch_bounds__(256, 1)
void gemm_mma_bf16x3(GemmPtrs p)
{
    extern __shared__ char smem[];
    const uint32_t sb = s2u(smem);
    const int z = blockIdx.z;
    const __nv_bfloat16* __restrict__ Ah = p.Ah[z];
    const __nv_bfloat16* __restrict__ Al = p.Al[z];
    const __nv_bfloat16* __restrict__ Bh = p.Bh[z];
    const __nv_bfloat16* __restrict__ Bl = p.Bl[z];
    const float* __restrict__ bias = p.bias[z];
    float* __restrict__ C = p.C[z];

    const int tid = threadIdx.x, wid = tid >> 5, lane = tid & 31;
    const int m0 = blockIdx.y << 7, n0 = blockIdx.x << 7;
    const int wm = wid & 1, wn = wid >> 1;          // warp tile: (wm*64, wn*32)

    const int a_row = (wm << 6) + (((lane >> 3) & 1) << 3) + (lane & 7); // + mi*16
    const int a_kh  = lane >> 4;
    const int b_row = (wn << 5) + (lane & 7);                            // + ni*8
    const int b_kh  = (lane >> 3) & 1;

    float acc[4][4][4];
    #pragma unroll
    for (int i = 0; i < 4; i++)
        #pragma unroll
        for (int j = 0; j < 4; j++)
            #pragma unroll
            for (int r = 0; r < 4; r++) acc[i][j][r] = 0.f;

    auto load_stage = [&](int chunk, int st) {
        const uint32_t base = sb + st * STAGE_BYTES;
        const int k0 = chunk << 6;
        #pragma unroll
        for (int i = 0; i < 4; i++) {
            const int idx = (i << 8) + tid;
            const int row = idx >> 3, c = idx & 7;
            const uint32_t so = SWZ((row << 7) + (c << 4));
            const size_t aoff = (((size_t)(m0 + row) << 9) + k0 + (c << 3)) * 2;
            const size_t boff = (((size_t)(n0 + row) << 9) + k0 + (c << 3)) * 2;
            cp16(base +         so, (const char*)Ah + aoff);
            cp16(base + 16384 + so, (const char*)Al + aoff);
            cp16(base + 32768 + so, (const char*)Bh + boff);
            cp16(base + 49152 + so, (const char*)Bl + boff);
        }
    };

    load_stage(0, 0);
    asm volatile("cp.async.commit_group;" ::: "memory");
    load_stage(1, 1);
    asm volatile("cp.async.commit_group;" ::: "memory");

    for (int c = 0; c < KCHUNKS; c++) {
        if (c < KCHUNKS - 1)
            asm volatile("cp.async.wait_group 1;" ::: "memory");
        else
            asm volatile("cp.async.wait_group 0;" ::: "memory");
        __syncthreads();

        if (c + 2 < KCHUNKS) {
            load_stage(c + 2, (c + 2) % 3);
            asm volatile("cp.async.commit_group;" ::: "memory");
        }

        const uint32_t stb = sb + (c % 3) * STAGE_BYTES;
        #pragma unroll
        for (int t = 0; t < 4; t++) {
            uint32_t ah[4][4], al2[4][4], bh[4][2], bl[4][2];
            #pragma unroll
            for (int mi = 0; mi < 4; mi++) {
                const int row = a_row + (mi << 4);
                const uint32_t so = SWZ((row << 7) + (((t << 1) + a_kh) << 4));
                ldsm4(ah[mi][0], ah[mi][1], ah[mi][2], ah[mi][3], stb + so);
            }
            #pragma unroll
            for (int ni = 0; ni < 4; ni++) {
                const int row = b_row + (ni << 3);
                const uint32_t so = SWZ((row << 7) + (((t << 1) + b_kh) << 4));
                ldsm2(bh[ni][0], bh[ni][1], stb + 32768 + so);
            }
            #pragma unroll
            for (int mi = 0; mi < 4; mi++)
                #pragma unroll
                for (int ni = 0; ni < 4; ni++)
                    mma_bf16(acc[mi][ni], ah[mi], bh[ni]);
            #pragma unroll
            for (int ni = 0; ni < 4; ni++) {
                const int row = b_row + (ni << 3);
                const uint32_t so = SWZ((row << 7) + (((t << 1) + b_kh) << 4));
                ldsm2(bl[ni][0], bl[ni][1], stb + 49152 + so);
            }
            #pragma unroll
            for (int mi = 0; mi < 4; mi++)
                #pragma unroll
                for (int ni = 0; ni < 4; ni++)
                    mma_bf16(acc[mi][ni], ah[mi], bl[ni]);
            #pragma unroll
            for (int mi = 0; mi < 4; mi++) {
                const int row = a_row + (mi << 4);
                const uint32_t so = SWZ((row << 7) + (((t << 1) + a_kh) << 4));
                ldsm4(al2[mi][0], al2[mi][1], al2[mi][2], al2[mi][3], stb + 16384 + so);
            }
            #pragma unroll
            for (int mi = 0; mi < 4; mi++)
                #pragma unroll
                for (int ni = 0; ni < 4; ni++)
                    mma_bf16(acc[mi][ni], al2[mi], bh[ni]);
        }
        // NOTE: no trailing __syncthreads needed — the top-of-loop sync at
        // iteration c+1 orders all reads of stage (c%3) before its next overwrite.
    }

    #pragma unroll
    for (int mi = 0; mi < 4; mi++) {
        const int row = m0 + (wm << 6) + (mi << 4) + (lane >> 2);
        #pragma unroll
        for (int ni = 0; ni < 4; ni++) {
            const int col = n0 + (wn << 5) + (ni << 3) + ((lane & 3) << 1);
            const float b0 = __ldg(bias + col), b1 = __ldg(bias + col + 1);
            float2 o0 = {acc[mi][ni][0] + b0, acc[mi][ni][1] + b1};
            float2 o1 = {acc[mi][ni][2] + b0, acc[mi][ni][3] + b1};
            *(float2*)(C + (size_t)row * DMODEL + col)       = o0;
            *(float2*)(C + (size_t)(row + 8) * DMODEL + col) = o1;
        }
    }
}

// ---------------- fused splits: 3 inputs, one launch, float4 vectorized -----
__global__ __launch_bounds__(256)
void split3(const float* __restrict__ x0, const float* __restrict__ x1,
            const float* __restrict__ x2,
            __nv_bfloat16* __restrict__ H, __nv_bfloat16* __restrict__ L)
{
    const int z = blockIdx.y;
    const float* __restrict__ X = (z == 0) ? x0 : (z == 1) ? x1 : x2;
    const int i = (blockIdx.x * 256 + threadIdx.x) << 2;
    const float4 v = *(const float4*)(X + i);

    const __nv_bfloat16 h0 = __float2bfloat16(v.x);
    const __nv_bfloat16 h1 = __float2bfloat16(v.y);
    const __nv_bfloat16 h2 = __float2bfloat16(v.z);
    const __nv_bfloat16 h3 = __float2bfloat16(v.w);
    const __nv_bfloat16 l0 = __float2bfloat16(v.x - __bfloat162float(h0));
    const __nv_bfloat16 l1 = __float2bfloat16(v.y - __bfloat162float(h1));
    const __nv_bfloat16 l2 = __float2bfloat16(v.z - __bfloat162float(h2));
    const __nv_bfloat16 l3 = __float2bfloat16(v.w - __bfloat162float(h3));

    __nv_bfloat162 hp0 = __halves2bfloat162(h0, h1);
    __nv_bfloat162 hp1 = __halves2bfloat162(h2, h3);
    __nv_bfloat162 lp0 = __halves2bfloat162(l0, l1);
    __nv_bfloat162 lp1 = __halves2bfloat162(l2, l3);
    uint2 hh = {*(uint32_t*)&hp0, *(uint32_t*)&hp1};
    uint2 ll = {*(uint32_t*)&lp0, *(uint32_t*)&lp1};
    *(uint2*)(H + (size_t)z * ND + i) = hh;
    *(uint2*)(L + (size_t)z * ND + i) = ll;
}

// ---------------- fused weight transpose+split: 4 weights, one launch -------
__global__ __launch_bounds__(256)
void transpose_split_all(const float* __restrict__ w0, const float* __restrict__ w1,
                         const float* __restrict__ w2, const float* __restrict__ w3,
                         __nv_bfloat16* __restrict__ Th, __nv_bfloat16* __restrict__ Tl)
{
    __shared__ float t[32][33];
    const int z = blockIdx.z;
    const float* __restrict__ W = (z == 0) ? w0 : (z == 1) ? w1 : (z == 2) ? w2 : w3;
    __nv_bfloat16* __restrict__ th = Th + (size_t)z * DD;
    __nv_bfloat16* __restrict__ tl = Tl + (size_t)z * DD;

    const int bx = blockIdx.x * 32, by = blockIdx.y * 32;
    const int x = bx + threadIdx.x;
    #pragma unroll
    for (int j = 0; j < 32; j += 8)
        t[threadIdx.y + j][threadIdx.x] = W[(size_t)(by + threadIdx.y + j) * DMODEL + x];
    __syncthreads();
    const int ox = by + threadIdx.x;
    #pragma unroll
    for (int j = 0; j < 32; j += 8) {
        const float v = t[threadIdx.x][threadIdx.y + j];
        const __nv_bfloat16 h = __float2bfloat16(v);
        const size_t o = (size_t)(bx + threadIdx.y + j) * DMODEL + ox;
        th[o] = h;
        tl[o] = __float2bfloat16(v - __bfloat162float(h));
    }
}

// ---------------- fused channel-wise attention + residual + bf16 split ------
__global__ __launch_bounds__(256, 8)
void attn_residual_split(const float* __restrict__ q, const float* __restrict__ k,
                         const float* __restrict__ v, const float* __restrict__ xq,
                         __nv_bfloat16* __restrict__ yh, __nv_bfloat16* __restrict__ yl)
{
    __shared__ float sk[8][DK];
    __shared__ float sv[8][DK];
    const int warp = threadIdx.x >> 5;
    const int lane = threadIdx.x & 31;
    const int gw   = blockIdx.x * 8 + warp;
    const int base = (gw >> 3) * DMODEL + (gw & 7) * DK;

    sk[warp][lane]      = k[base + lane];
    sk[warp][lane + 32] = k[base + lane + 32];
    sv[warp][lane]      = v[base + lane];
    sv[warp][lane + 32] = v[base + lane + 32];
    // fold 1/sqrt(d_k) * log2(e) into the per-channel scale: exp(x) = exp2(x*log2e)
    const float SCL = 0.125f * 1.4426950408889634f;
    const float a0 = q[base + lane]      * SCL;
    const float a1 = q[base + lane + 32] * SCL;
    __syncwarp();

    float num0 = 0.f, den0 = 0.f, num1 = 0.f, den1 = 0.f;
    #pragma unroll 8
    for (int j = 0; j < DK; j++) {
        const float kj = sk[warp][j];
        const float vj = sv[warp][j];
        const float e0 = exp2f(a0 * kj);
        const float e1 = exp2f(a1 * kj);
        num0 = fmaf(e0, vj, num0);
        den0 += e0;
        num1 = fmaf(e1, vj, num1);
        den1 += e1;
    }
    const float y0 = xq[base + lane]      - __fdividef(num0, den0);
    const float y1 = xq[base + lane + 32] - __fdividef(num1, den1);
    const __nv_bfloat16 h0 = __float2bfloat16(y0);
    const __nv_bfloat16 h1 = __float2bfloat16(y1);
    yh[base + lane]      = h0;
    yl[base + lane]      = __float2bfloat16(y0 - __bfloat162float(h0));
    yh[base + lane + 32] = h1;
    yl[base + lane + 32] = __float2bfloat16(y1 - __bfloat162float(h1));
}

// ---------------- launch ------------------------------------------------------
extern "C" void kernel_launch(void* const* d_in, const int* in_sizes, int n_in,
                              void* d_out, int out_size)
{
    const float* x_q = (const float*)d_in[0];
    const float* x_k = (const float*)d_in[1];
    const float* x_v = (const float*)d_in[2];
    const float* Wq = (const float*)d_in[3];
    const float* bq = (const float*)d_in[4];
    const float* Wk = (const float*)d_in[5];
    const float* bk = (const float*)d_in[6];
    const float* Wv = (const float*)d_in[7];
    const float* bv = (const float*)d_in[8];
    const float* Wo = (const float*)d_in[9];
    const float* bo = (const float*)d_in[10];
    float* out = (float*)d_out;

    cudaFuncSetAttribute(gemm_mma_bf16x3, cudaFuncAttributeMaxDynamicSharedMemorySize,
                         GSMEM_TOTAL);

    float *gq, *gk, *gv;
    __nv_bfloat16 *xh, *xl, *wth, *wtl, *yh, *yl;
    cudaGetSymbolAddress((void**)&gq, g_q);
    cudaGetSymbolAddress((void**)&gk, g_k);
    cudaGetSymbolAddress((void**)&gv, g_v);
    cudaGetSymbolAddress((void**)&xh, g_xh);
    cudaGetSymbolAddress((void**)&xl, g_xl);
    cudaGetSymbolAddress((void**)&wth, g_wth);
    cudaGetSymbolAddress((void**)&wtl, g_wtl);
    cudaGetSymbolAddress((void**)&yh, g_yh);
    cudaGetSymbolAddress((void**)&yl, g_yl);

    // 1) weight transposes + splits (one launch, 4 weights)
    transpose_split_all<<<dim3(16, 16, 4), dim3(32, 8)>>>(Wq, Wk, Wv, Wo, wth, wtl);

    // 2) input splits (one launch, 3 inputs)
    split3<<<dim3(ND / 1024, 3), 256>>>(x_q, x_k, x_v, xh, xl);

    // 3) Q/K/V projection GEMMs in one launch (grid.z = 3)
    GemmPtrs pq;
    for (int z = 0; z < 3; z++) {
        pq.Ah[z] = xh + (size_t)z * ND;
        pq.Al[z] = xl + (size_t)z * ND;
        pq.Bh[z] = wth + (size_t)z * DD;
        pq.Bl[z] = wtl + (size_t)z * DD;
    }
    pq.bias[0] = bq; pq.bias[1] = bk; pq.bias[2] = bv;
    pq.C[0] = gq; pq.C[1] = gk; pq.C[2] = gv;
    gemm_mma_bf16x3<<<dim3(4, 32, 3), 256, GSMEM_TOTAL>>>(pq);

    // 4) attention + residual + split
    attn_residual_split<<<NROWS, 256>>>(gq, gk, gv, x_q, yh, yl);

    // 5) output projection
    GemmPtrs po;
    po.Ah[0] = yh;  po.Al[0] = yl;
    po.Bh[0] = wth + (size_t)3 * DD;
    po.Bl[0] = wtl + (size_t)3 * DD;
    po.bias[0] = bo;
    po.C[0] = out;
    po.Ah[1] = po.Ah[2] = yh; po.Al[1] = po.Al[2] = yl;
    po.Bh[1] = po.Bh[2] = po.Bh[0]; po.Bl[1] = po.Bl[2] = po.Bl[0];
    po.bias[1] = po.bias[2] = bo;
    po.C[1] = po.C[2] = out;
    gemm_mma_bf16x3<<<dim3(4, 32, 1), 256, GSMEM_TOTAL>>>(po);
}

// round 5
// speedup vs baseline: 3.2803x; 1.2291x over previous
#include <cuda_runtime.h>
#include <cuda_fp16.h>
#include <cstdint>

#define NROWS  4096
#define DMODEL 512
#define DK     64
#define ND     (NROWS * DMODEL)
#define DD     (DMODEL * DMODEL)

// ---------------- scratch (device globals; allocation-free) -----------------
__device__ float g_q[ND];
__device__ float g_k[ND];
__device__ float g_v[ND];
__device__ __half g_xh[3][ND];          // fp16 activations (hi only)
__device__ __half g_wth[4][DD];         // weight^T hi
__device__ __half g_wtl[4][DD];         // weight^T lo
__device__ __half g_yh[ND];             // attention output (fp16)

// ---------------- PTX helpers ----------------
static __device__ __forceinline__ uint32_t s2u(const void* p) {
    uint32_t a;
    asm("{ .reg .u64 t; cvta.to.shared.u64 t, %1; cvt.u32.u64 %0, t; }" : "=r"(a) : "l"(p));
    return a;
}
static __device__ __forceinline__ void cp16(uint32_t s, const void* g) {
    asm volatile("cp.async.cg.shared.global [%0], [%1], 16;" :: "r"(s), "l"(g));
}
static __device__ __forceinline__ void ldsm4(uint32_t& r0, uint32_t& r1, uint32_t& r2,
                                             uint32_t& r3, uint32_t a) {
    asm volatile("ldmatrix.sync.aligned.m8n8.x4.shared.b16 {%0,%1,%2,%3}, [%4];"
                 : "=r"(r0), "=r"(r1), "=r"(r2), "=r"(r3) : "r"(a));
}
static __device__ __forceinline__ void ldsm2(uint32_t& r0, uint32_t& r1, uint32_t a) {
    asm volatile("ldmatrix.sync.aligned.m8n8.x2.shared.b16 {%0,%1}, [%2];"
                 : "=r"(r0), "=r"(r1) : "r"(a));
}
static __device__ __forceinline__ void mma_f16(float* c, const uint32_t* a, const uint32_t* b) {
    asm volatile(
        "mma.sync.aligned.m16n8k16.row.col.f32.f16.f16.f32 "
        "{%0,%1,%2,%3}, {%4,%5,%6,%7}, {%8,%9}, {%0,%1,%2,%3};"
        : "+f"(c[0]), "+f"(c[1]), "+f"(c[2]), "+f"(c[3])
        : "r"(a[0]), "r"(a[1]), "r"(a[2]), "r"(a[3]), "r"(b[0]), "r"(b[1]));
}
#define SWZ(x) ((x) ^ (((x) >> 3) & 0x70))

// ---------------- GEMM: C[4096,512] = Ah @ (Bh+Bl)^T + bias ------------------
// fp16x2: C = Ah*Bh + Ah*Bl (fp32 accum). A fp16 [M,K] row-major;
// B pre-transposed fp16 hi/lo [N,K] K-major. CTA tile 128x128, 256 threads
// (8 warps, warp tile 64x32), K chunks of 64, 3-stage cp.async pipeline.
#define KCHUNKS 8
#define STAGE_BYTES 49152     // Ah(16K) | Bh(16K) | Bl(16K), rows of 128B
#define GSMEM_TOTAL (3 * STAGE_BYTES)

struct GemmPtrs {
    const __half* Ah[3];
    const __half* Bh[3];
    const __half* Bl[3];
    const float*  bias[3];
    float*        C[3];
};

__global__ __launch_bounds__(256, 1)
void gemm_mma_f16x2(GemmPtrs p)
{
    extern __shared__ char smem[];
    const uint32_t sb = s2u(smem);
    const int z = blockIdx.z;
    const __half* __restrict__ Ah = p.Ah[z];
    const __half* __restrict__ Bh = p.Bh[z];
    const __half* __restrict__ Bl = p.Bl[z];
    const float* __restrict__ bias = p.bias[z];
    float* __restrict__ C = p.C[z];

    const int tid = threadIdx.x, wid = tid >> 5, lane = tid & 31;
    const int m0 = blockIdx.y << 7, n0 = blockIdx.x << 7;
    const int wm = wid & 1, wn = wid >> 1;          // warp tile: (wm*64, wn*32)

    const int a_row = (wm << 6) + (((lane >> 3) & 1) << 3) + (lane & 7); // + mi*16
    const int a_kh  = lane >> 4;
    const int b_row = (wn << 5) + (lane & 7);                            // + ni*8
    const int b_kh  = (lane >> 3) & 1;

    float acc[4][4][4];
    #pragma unroll
    for (int i = 0; i < 4; i++)
        #pragma unroll
        for (int j = 0; j < 4; j++)
            #pragma unroll
            for (int r = 0; r < 4; r++) acc[i][j][r] = 0.f;

    auto load_stage = [&](int chunk, int st) {
        const uint32_t base = sb + st * STAGE_BYTES;
        const int k0 = chunk << 6;
        #pragma unroll
        for (int i = 0; i < 4; i++) {
            const int idx = (i << 8) + tid;
            const int row = idx >> 3, c = idx & 7;
            const uint32_t so = SWZ((row << 7) + (c << 4));
            const size_t aoff = (((size_t)(m0 + row) << 9) + k0 + (c << 3)) * 2;
            const size_t boff = (((size_t)(n0 + row) << 9) + k0 + (c << 3)) * 2;
            cp16(base +         so, (const char*)Ah + aoff);
            cp16(base + 16384 + so, (const char*)Bh + boff);
            cp16(base + 32768 + so, (const char*)Bl + boff);
        }
    };

    load_stage(0, 0);
    asm volatile("cp.async.commit_group;" ::: "memory");
    load_stage(1, 1);
    asm volatile("cp.async.commit_group;" ::: "memory");

    for (int c = 0; c < KCHUNKS; c++) {
        if (c < KCHUNKS - 1)
            asm volatile("cp.async.wait_group 1;" ::: "memory");
        else
            asm volatile("cp.async.wait_group 0;" ::: "memory");
        __syncthreads();

        if (c + 2 < KCHUNKS) {
            load_stage(c + 2, (c + 2) % 3);
            asm volatile("cp.async.commit_group;" ::: "memory");
        }

        const uint32_t stb = sb + (c % 3) * STAGE_BYTES;
        #pragma unroll
        for (int t = 0; t < 4; t++) {
            uint32_t ah[4][4], bh[4][2], bl[4][2];
            #pragma unroll
            for (int mi = 0; mi < 4; mi++) {
                const int row = a_row + (mi << 4);
                const uint32_t so = SWZ((row << 7) + (((t << 1) + a_kh) << 4));
                ldsm4(ah[mi][0], ah[mi][1], ah[mi][2], ah[mi][3], stb + so);
            }
            #pragma unroll
            for (int ni = 0; ni < 4; ni++) {
                const int row = b_row + (ni << 3);
                const uint32_t so = SWZ((row << 7) + (((t << 1) + b_kh) << 4));
                ldsm2(bh[ni][0], bh[ni][1], stb + 16384 + so);
            }
            #pragma unroll
            for (int mi = 0; mi < 4; mi++)
                #pragma unroll
                for (int ni = 0; ni < 4; ni++)
                    mma_f16(acc[mi][ni], ah[mi], bh[ni]);
            #pragma unroll
            for (int ni = 0; ni < 4; ni++) {
                const int row = b_row + (ni << 3);
                const uint32_t so = SWZ((row << 7) + (((t << 1) + b_kh) << 4));
                ldsm2(bl[ni][0], bl[ni][1], stb + 32768 + so);
            }
            #pragma unroll
            for (int mi = 0; mi < 4; mi++)
                #pragma unroll
                for (int ni = 0; ni < 4; ni++)
                    mma_f16(acc[mi][ni], ah[mi], bl[ni]);
        }
        // top-of-loop sync at iter c+1 protects stage reuse; no trailing sync.
    }

    #pragma unroll
    for (int mi = 0; mi < 4; mi++) {
        const int row = m0 + (wm << 6) + (mi << 4) + (lane >> 2);
        #pragma unroll
        for (int ni = 0; ni < 4; ni++) {
            const int col = n0 + (wn << 5) + (ni << 3) + ((lane & 3) << 1);
            const float b0 = __ldg(bias + col), b1 = __ldg(bias + col + 1);
            float2 o0 = {acc[mi][ni][0] + b0, acc[mi][ni][1] + b1};
            float2 o1 = {acc[mi][ni][2] + b0, acc[mi][ni][3] + b1};
            *(float2*)(C + (size_t)row * DMODEL + col)       = o0;
            *(float2*)(C + (size_t)(row + 8) * DMODEL + col) = o1;
        }
    }
}

// ---------------- fused preprocessing: one launch -----------------------------
// blocks [0, 1024):  weight z = bx>>8 transpose + fp16 hi/lo split (32x32 tiles)
// blocks [1024, 7168): activation cvt fp32->fp16, tensor z = (bx-1024)/2048
__global__ __launch_bounds__(256)
void preprocess(const float* __restrict__ w0, const float* __restrict__ w1,
                const float* __restrict__ w2, const float* __restrict__ w3,
                const float* __restrict__ x0, const float* __restrict__ x1,
                const float* __restrict__ x2,
                __half* __restrict__ Th, __half* __restrict__ Tl,
                __half* __restrict__ H)
{
    const int bx = blockIdx.x, tid = threadIdx.x;
    if (bx < 1024) {
        __shared__ float t[32][33];
        const int z = bx >> 8, b = bx & 255;
        const float* __restrict__ W = (z == 0) ? w0 : (z == 1) ? w1 : (z == 2) ? w2 : w3;
        __half* __restrict__ th = Th + (size_t)z * DD;
        __half* __restrict__ tl = Tl + (size_t)z * DD;
        const int bxe = (b & 15) * 32, bye = (b >> 4) * 32;
        const int tx = tid & 31, ty = tid >> 5;
        const int x = bxe + tx;
        #pragma unroll
        for (int j = 0; j < 32; j += 8)
            t[ty + j][tx] = W[(size_t)(bye + ty + j) * DMODEL + x];
        __syncthreads();
        const int ox = bye + tx;
        #pragma unroll
        for (int j = 0; j < 32; j += 8) {
            const float v = t[tx][ty + j];
            const __half h = __float2half(v);
            const size_t o = (size_t)(bxe + ty + j) * DMODEL + ox;
            th[o] = h;
            tl[o] = __float2half(v - __half2float(h));
        }
    } else {
        const int idx = bx - 1024;
        const int z = idx >> 11;                   // /2048
        const int blk = idx & 2047;
        const float* __restrict__ X = (z == 0) ? x0 : (z == 1) ? x1 : x2;
        const int i = (blk * 256 + tid) << 2;
        const float4 v = *(const float4*)(X + i);
        __half2 p0 = __floats2half2_rn(v.x, v.y);
        __half2 p1 = __floats2half2_rn(v.z, v.w);
        uint2 o = {*(uint32_t*)&p0, *(uint32_t*)&p1};
        *(uint2*)(H + (size_t)z * ND + i) = o;
    }
}

// ---------------- fused channel-wise attention + residual -> fp16 -----------
__global__ __launch_bounds__(256, 8)
void attn_residual_h(const float* __restrict__ q, const float* __restrict__ k,
                     const float* __restrict__ v, const float* __restrict__ xq,
                     __half* __restrict__ yh)
{
    __shared__ float sk[8][DK];
    __shared__ float sv[8][DK];
    const int warp = threadIdx.x >> 5;
    const int lane = threadIdx.x & 31;
    const int gw   = blockIdx.x * 8 + warp;
    const int base = (gw >> 3) * DMODEL + (gw & 7) * DK;

    sk[warp][lane]      = k[base + lane];
    sk[warp][lane + 32] = k[base + lane + 32];
    sv[warp][lane]      = v[base + lane];
    sv[warp][lane + 32] = v[base + lane + 32];
    const float SCL = 0.125f * 1.4426950408889634f;   // 1/sqrt(dk) * log2(e)
    const float a0 = q[base + lane]      * SCL;
    const float a1 = q[base + lane + 32] * SCL;
    __syncwarp();

    float num0 = 0.f, den0 = 0.f, num1 = 0.f, den1 = 0.f;
    #pragma unroll 8
    for (int j = 0; j < DK; j++) {
        const float kj = sk[warp][j];
        const float vj = sv[warp][j];
        const float e0 = exp2f(a0 * kj);
        const float e1 = exp2f(a1 * kj);
        num0 = fmaf(e0, vj, num0);
        den0 += e0;
        num1 = fmaf(e1, vj, num1);
        den1 += e1;
    }
    const float y0 = xq[base + lane]      - __fdividef(num0, den0);
    const float y1 = xq[base + lane + 32] - __fdividef(num1, den1);
    yh[base + lane]      = __float2half(y0);
    yh[base + lane + 32] = __float2half(y1);
}

// ---------------- launch ------------------------------------------------------
extern "C" void kernel_launch(void* const* d_in, const int* in_sizes, int n_in,
                              void* d_out, int out_size)
{
    const float* x_q = (const float*)d_in[0];
    const float* x_k = (const float*)d_in[1];
    const float* x_v = (const float*)d_in[2];
    const float* Wq = (const float*)d_in[3];
    const float* bq = (const float*)d_in[4];
    const float* Wk = (const float*)d_in[5];
    const float* bk = (const float*)d_in[6];
    const float* Wv = (const float*)d_in[7];
    const float* bv = (const float*)d_in[8];
    const float* Wo = (const float*)d_in[9];
    const float* bo = (const float*)d_in[10];
    float* out = (float*)d_out;

    cudaFuncSetAttribute(gemm_mma_f16x2, cudaFuncAttributeMaxDynamicSharedMemorySize,
                         GSMEM_TOTAL);

    float *gq, *gk, *gv;
    __half *xh, *wth, *wtl, *yh;
    cudaGetSymbolAddress((void**)&gq, g_q);
    cudaGetSymbolAddress((void**)&gk, g_k);
    cudaGetSymbolAddress((void**)&gv, g_v);
    cudaGetSymbolAddress((void**)&xh, g_xh);
    cudaGetSymbolAddress((void**)&wth, g_wth);
    cudaGetSymbolAddress((void**)&wtl, g_wtl);
    cudaGetSymbolAddress((void**)&yh, g_yh);

    // 1) all preprocessing in one launch (4 weight transposes + 3 cvt)
    preprocess<<<1024 + 3 * (ND / 1024), 256>>>(Wq, Wk, Wv, Wo, x_q, x_k, x_v,
                                                wth, wtl, xh);

    // 2) Q/K/V projection GEMMs in one launch (grid.z = 3)
    GemmPtrs pq;
    for (int z = 0; z < 3; z++) {
        pq.Ah[z] = xh + (size_t)z * ND;
        pq.Bh[z] = wth + (size_t)z * DD;
        pq.Bl[z] = wtl + (size_t)z * DD;
    }
    pq.bias[0] = bq; pq.bias[1] = bk; pq.bias[2] = bv;
    pq.C[0] = gq; pq.C[1] = gk; pq.C[2] = gv;
    gemm_mma_f16x2<<<dim3(4, 32, 3), 256, GSMEM_TOTAL>>>(pq);

    // 3) attention + residual (-> fp16)
    attn_residual_h<<<NROWS, 256>>>(gq, gk, gv, x_q, yh);

    // 4) output projection
    GemmPtrs po;
    po.Ah[0] = yh;
    po.Bh[0] = wth + (size_t)3 * DD;
    po.Bl[0] = wtl + (size_t)3 * DD;
    po.bias[0] = bo;
    po.C[0] = out;
    po.Ah[1] = po.Ah[2] = po.Ah[0];
    po.Bh[1] = po.Bh[2] = po.Bh[0];
    po.Bl[1] = po.Bl[2] = po.Bl[0];
    po.bias[1] = po.bias[2] = bo;
    po.C[1] = po.C[2] = out;
    gemm_mma_f16x2<<<dim3(4, 32, 1), 256, GSMEM_TOTAL>>>(po);
}

// round 6
// speedup vs baseline: 3.4373x; 1.0479x over previous
#include <cuda_runtime.h>
#include <cuda_fp16.h>
#include <cstdint>

#define NROWS  4096
#define DMODEL 512
#define DK     64
#define ND     (NROWS * DMODEL)
#define DD     (DMODEL * DMODEL)

// ---------------- scratch (device globals; allocation-free) -----------------
__device__ float g_q[ND];
__device__ float g_k[ND];
__device__ float g_v[ND];
__device__ __half g_xh[3][ND];          // fp16 activations (hi only)
__device__ __half g_wth[4][DD];         // weight^T hi
__device__ __half g_wtl[4][DD];         // weight^T lo
__device__ __half g_yh[ND];             // attention output (fp16)

// ---------------- PTX helpers ----------------
static __device__ __forceinline__ uint32_t s2u(const void* p) {
    uint32_t a;
    asm("{ .reg .u64 t; cvta.to.shared.u64 t, %1; cvt.u32.u64 %0, t; }" : "=r"(a) : "l"(p));
    return a;
}
static __device__ __forceinline__ void cp16(uint32_t s, const void* g) {
    asm volatile("cp.async.cg.shared.global [%0], [%1], 16;" :: "r"(s), "l"(g));
}
static __device__ __forceinline__ void ldsm4(uint32_t& r0, uint32_t& r1, uint32_t& r2,
                                             uint32_t& r3, uint32_t a) {
    asm volatile("ldmatrix.sync.aligned.m8n8.x4.shared.b16 {%0,%1,%2,%3}, [%4];"
                 : "=r"(r0), "=r"(r1), "=r"(r2), "=r"(r3) : "r"(a));
}
static __device__ __forceinline__ void mma_f16(float* c, const uint32_t* a, const uint32_t* b) {
    asm volatile(
        "mma.sync.aligned.m16n8k16.row.col.f32.f16.f16.f32 "
        "{%0,%1,%2,%3}, {%4,%5,%6,%7}, {%8,%9}, {%0,%1,%2,%3};"
        : "+f"(c[0]), "+f"(c[1]), "+f"(c[2]), "+f"(c[3])
        : "r"(a[0]), "r"(a[1]), "r"(a[2]), "r"(a[3]), "r"(b[0]), "r"(b[1]));
}
#define SWZ(x) ((x) ^ (((x) >> 3) & 0x70))

// ---------------- GEMM: C[4096,512] = Ah @ (Bh+Bl)^T + bias ------------------
// fp16x2: C = Ah*Bh + Ah*Bl (fp32 accum). CTA tile 128x128, 512 threads
// (16 warps, warp tile 32x32, 4 warps/SMSP for latency hiding), K chunks of 64,
// 3-stage cp.async pipeline.
#define KCHUNKS 8
#define STAGE_BYTES 49152     // Ah(16K) | Bh(16K) | Bl(16K), rows of 128B
#define GSMEM_TOTAL (3 * STAGE_BYTES)

struct GemmPtrs {
    const __half* Ah[3];
    const __half* Bh[3];
    const __half* Bl[3];
    const float*  bias[3];
    float*        C[3];
};

__global__ __launch_bounds__(512, 1)
void gemm_mma_f16x2(GemmPtrs p)
{
    extern __shared__ char smem[];
    const uint32_t sb = s2u(smem);
    const int z = blockIdx.z;
    const __half* __restrict__ Ah = p.Ah[z];
    const __half* __restrict__ Bh = p.Bh[z];
    const __half* __restrict__ Bl = p.Bl[z];
    const float* __restrict__ bias = p.bias[z];
    float* __restrict__ C = p.C[z];

    const int tid = threadIdx.x, wid = tid >> 5, lane = tid & 31;
    const int m0 = blockIdx.y << 7, n0 = blockIdx.x << 7;
    const int wm = wid & 3, wn = wid >> 2;          // warp tile (wm*32, wn*32)

    // ldmatrix source rows
    const int a_row  = (wm << 5) + (lane & 15);                          // + mi*16
    const int a_kh   = lane >> 4;
    const int b_row0 = (wn << 5) + (((lane >> 4) & 1) << 3) + (lane & 7); // + pr*16
    const int b_kh   = (lane >> 3) & 1;

    float acc[2][4][4];
    #pragma unroll
    for (int i = 0; i < 2; i++)
        #pragma unroll
        for (int j = 0; j < 4; j++)
            #pragma unroll
            for (int r = 0; r < 4; r++) acc[i][j][r] = 0.f;

    auto load_stage = [&](int chunk, int st) {
        const uint32_t base = sb + st * STAGE_BYTES;
        const int k0 = chunk << 6;
        #pragma unroll
        for (int i = 0; i < 2; i++) {
            const int idx = (i << 9) + tid;
            const int row = idx >> 3, c = idx & 7;
            const uint32_t so = SWZ((row << 7) + (c << 4));
            const size_t aoff = (((size_t)(m0 + row) << 9) + k0 + (c << 3)) * 2;
            const size_t boff = (((size_t)(n0 + row) << 9) + k0 + (c << 3)) * 2;
            cp16(base +         so, (const char*)Ah + aoff);
            cp16(base + 16384 + so, (const char*)Bh + boff);
            cp16(base + 32768 + so, (const char*)Bl + boff);
        }
    };

    load_stage(0, 0);
    asm volatile("cp.async.commit_group;" ::: "memory");
    load_stage(1, 1);
    asm volatile("cp.async.commit_group;" ::: "memory");

    for (int c = 0; c < KCHUNKS; c++) {
        if (c < KCHUNKS - 1)
            asm volatile("cp.async.wait_group 1;" ::: "memory");
        else
            asm volatile("cp.async.wait_group 0;" ::: "memory");
        __syncthreads();

        if (c + 2 < KCHUNKS) {
            load_stage(c + 2, (c + 2) % 3);
            asm volatile("cp.async.commit_group;" ::: "memory");
        }

        const uint32_t stb = sb + (c % 3) * STAGE_BYTES;
        #pragma unroll
        for (int t = 0; t < 4; t++) {
            uint32_t ah[2][4], bh[4][2], bl[4][2];
            #pragma unroll
            for (int mi = 0; mi < 2; mi++) {
                const int row = a_row + (mi << 4);
                const uint32_t so = SWZ((row << 7) + (((t << 1) + a_kh) << 4));
                ldsm4(ah[mi][0], ah[mi][1], ah[mi][2], ah[mi][3], stb + so);
            }
            #pragma unroll
            for (int pr = 0; pr < 2; pr++) {
                const int row = b_row0 + (pr << 4);
                const uint32_t so = SWZ((row << 7) + (((t << 1) + b_kh) << 4));
                ldsm4(bh[2 * pr][0], bh[2 * pr][1], bh[2 * pr + 1][0], bh[2 * pr + 1][1],
                      stb + 16384 + so);
            }
            #pragma unroll
            for (int mi = 0; mi < 2; mi++)
                #pragma unroll
                for (int ni = 0; ni < 4; ni++)
                    mma_f16(acc[mi][ni], ah[mi], bh[ni]);
            #pragma unroll
            for (int pr = 0; pr < 2; pr++) {
                const int row = b_row0 + (pr << 4);
                const uint32_t so = SWZ((row << 7) + (((t << 1) + b_kh) << 4));
                ldsm4(bl[2 * pr][0], bl[2 * pr][1], bl[2 * pr + 1][0], bl[2 * pr + 1][1],
                      stb + 32768 + so);
            }
            #pragma unroll
            for (int mi = 0; mi < 2; mi++)
                #pragma unroll
                for (int ni = 0; ni < 4; ni++)
                    mma_f16(acc[mi][ni], ah[mi], bl[ni]);
        }
        // top-of-loop sync at iter c+1 protects stage reuse; no trailing sync.
    }

    #pragma unroll
    for (int mi = 0; mi < 2; mi++) {
        const int row = m0 + (wm << 5) + (mi << 4) + (lane >> 2);
        #pragma unroll
        for (int ni = 0; ni < 4; ni++) {
            const int col = n0 + (wn << 5) + (ni << 3) + ((lane & 3) << 1);
            const float b0 = __ldg(bias + col), b1 = __ldg(bias + col + 1);
            float2 o0 = {acc[mi][ni][0] + b0, acc[mi][ni][1] + b1};
            float2 o1 = {acc[mi][ni][2] + b0, acc[mi][ni][3] + b1};
            *(float2*)(C + (size_t)row * DMODEL + col)       = o0;
            *(float2*)(C + (size_t)(row + 8) * DMODEL + col) = o1;
        }
    }
}

// ---------------- fused preprocessing: one launch -----------------------------
__global__ __launch_bounds__(256)
void preprocess(const float* __restrict__ w0, const float* __restrict__ w1,
                const float* __restrict__ w2, const float* __restrict__ w3,
                const float* __restrict__ x0, const float* __restrict__ x1,
                const float* __restrict__ x2,
                __half* __restrict__ Th, __half* __restrict__ Tl,
                __half* __restrict__ H)
{
    const int bx = blockIdx.x, tid = threadIdx.x;
    if (bx < 1024) {
        __shared__ float t[32][33];
        const int z = bx >> 8, b = bx & 255;
        const float* __restrict__ W = (z == 0) ? w0 : (z == 1) ? w1 : (z == 2) ? w2 : w3;
        __half* __restrict__ th = Th + (size_t)z * DD;
        __half* __restrict__ tl = Tl + (size_t)z * DD;
        const int bxe = (b & 15) * 32, bye = (b >> 4) * 32;
        const int tx = tid & 31, ty = tid >> 5;
        const int x = bxe + tx;
        #pragma unroll
        for (int j = 0; j < 32; j += 8)
            t[ty + j][tx] = W[(size_t)(bye + ty + j) * DMODEL + x];
        __syncthreads();
        const int ox = bye + tx;
        #pragma unroll
        for (int j = 0; j < 32; j += 8) {
            const float v = t[tx][ty + j];
            const __half h = __float2half(v);
            const size_t o = (size_t)(bxe + ty + j) * DMODEL + ox;
            th[o] = h;
            tl[o] = __float2half(v - __half2float(h));
        }
    } else {
        const int idx = bx - 1024;
        const int z = idx >> 11;
        const int blk = idx & 2047;
        const float* __restrict__ X = (z == 0) ? x0 : (z == 1) ? x1 : x2;
        const int i = (blk * 256 + tid) << 2;
        const float4 v = *(const float4*)(X + i);
        __half2 p0 = __floats2half2_rn(v.x, v.y);
        __half2 p1 = __floats2half2_rn(v.z, v.w);
        uint2 o = {*(uint32_t*)&p0, *(uint32_t*)&p1};
        *(uint2*)(H + (size_t)z * ND + i) = o;
    }
}

// ---------------- fused attention + residual: fp16x2 exp (MUFU halved) ------
__global__ __launch_bounds__(256, 8)
void attn_residual_h(const float* __restrict__ q, const float* __restrict__ k,
                     const float* __restrict__ v, const float* __restrict__ xq,
                     __half* __restrict__ yh)
{
    __shared__ __half2 sk2[8][DK];
    __shared__ __half2 sv2[8][DK];
    const int warp = threadIdx.x >> 5;
    const int lane = threadIdx.x & 31;
    const int gw   = blockIdx.x * 8 + warp;
    const int base = (gw >> 3) * DMODEL + (gw & 7) * DK;

    sk2[warp][lane]      = __float2half2_rn(k[base + lane]);
    sk2[warp][lane + 32] = __float2half2_rn(k[base + lane + 32]);
    sv2[warp][lane]      = __float2half2_rn(v[base + lane]);
    sv2[warp][lane + 32] = __float2half2_rn(v[base + lane + 32]);
    const float SCL = 0.125f * 1.4426950408889634f;   // 1/sqrt(dk) * log2(e)
    const __half2 a01 = __floats2half2_rn(q[base + lane] * SCL,
                                          q[base + lane + 32] * SCL);
    __syncwarp();

    // chunked fp16x2 accumulation: flush partials to fp32 every 16 j's
    float num0 = 0.f, num1 = 0.f, den0 = 0.f, den1 = 0.f;
    #pragma unroll
    for (int jc = 0; jc < 4; jc++) {
        __half2 np = __float2half2_rn(0.f);
        __half2 dp = __float2half2_rn(0.f);
        #pragma unroll
        for (int j16 = 0; j16 < 16; j16++) {
            const int j = (jc << 4) + j16;
            const __half2 e = h2exp2(__hmul2(a01, sk2[warp][j]));
            np = __hfma2(e, sv2[warp][j], np);
            dp = __hadd2(dp, e);
        }
        const float2 nf = __half22float2(np);
        const float2 df = __half22float2(dp);
        num0 += nf.x; num1 += nf.y;
        den0 += df.x; den1 += df.y;
    }
    const float y0 = xq[base + lane]      - __fdividef(num0, den0);
    const float y1 = xq[base + lane + 32] - __fdividef(num1, den1);
    yh[base + lane]      = __float2half(y0);
    yh[base + lane + 32] = __float2half(y1);
}

// ---------------- launch ------------------------------------------------------
extern "C" void kernel_launch(void* const* d_in, const int* in_sizes, int n_in,
                              void* d_out, int out_size)
{
    const float* x_q = (const float*)d_in[0];
    const float* x_k = (const float*)d_in[1];
    const float* x_v = (const float*)d_in[2];
    const float* Wq = (const float*)d_in[3];
    const float* bq = (const float*)d_in[4];
    const float* Wk = (const float*)d_in[5];
    const float* bk = (const float*)d_in[6];
    const float* Wv = (const float*)d_in[7];
    const float* bv = (const float*)d_in[8];
    const float* Wo = (const float*)d_in[9];
    const float* bo = (const float*)d_in[10];
    float* out = (float*)d_out;

    cudaFuncSetAttribute(gemm_mma_f16x2, cudaFuncAttributeMaxDynamicSharedMemorySize,
                         GSMEM_TOTAL);

    float *gq, *gk, *gv;
    __half *xh, *wth, *wtl, *yh;
    cudaGetSymbolAddress((void**)&gq, g_q);
    cudaGetSymbolAddress((void**)&gk, g_k);
    cudaGetSymbolAddress((void**)&gv, g_v);
    cudaGetSymbolAddress((void**)&xh, g_xh);
    cudaGetSymbolAddress((void**)&wth, g_wth);
    cudaGetSymbolAddress((void**)&wtl, g_wtl);
    cudaGetSymbolAddress((void**)&yh, g_yh);

    // 1) all preprocessing in one launch (4 weight transposes + 3 cvt)
    preprocess<<<1024 + 3 * (ND / 1024), 256>>>(Wq, Wk, Wv, Wo, x_q, x_k, x_v,
                                                wth, wtl, xh);

    // 2) Q/K/V projection GEMMs in one launch (grid.z = 3)
    GemmPtrs pq;
    for (int z = 0; z < 3; z++) {
        pq.Ah[z] = xh + (size_t)z * ND;
        pq.Bh[z] = wth + (size_t)z * DD;
        pq.Bl[z] = wtl + (size_t)z * DD;
    }
    pq.bias[0] = bq; pq.bias[1] = bk; pq.bias[2] = bv;
    pq.C[0] = gq; pq.C[1] = gk; pq.C[2] = gv;
    gemm_mma_f16x2<<<dim3(4, 32, 3), 512, GSMEM_TOTAL>>>(pq);

    // 3) attention + residual (-> fp16)
    attn_residual_h<<<NROWS, 256>>>(gq, gk, gv, x_q, yh);

    // 4) output projection
    GemmPtrs po;
    po.Ah[0] = yh;
    po.Bh[0] = wth + (size_t)3 * DD;
    po.Bl[0] = wtl + (size_t)3 * DD;
    po.bias[0] = bo;
    po.C[0] = out;
    po.Ah[1] = po.Ah[2] = po.Ah[0];
    po.Bh[1] = po.Bh[2] = po.Bh[0];
    po.Bl[1] = po.Bl[2] = po.Bl[0];
    po.bias[1] = po.bias[2] = bo;
    po.C[1] = po.C[2] = out;
    gemm_mma_f16x2<<<dim3(4, 32, 1), 512, GSMEM_TOTAL>>>(po);
}

// round 7
// speedup vs baseline: 4.3287x; 1.2593x over previous
#include <cuda_runtime.h>
#include <cuda_fp16.h>
#include <cstdint>

#define NROWS  4096
#define DMODEL 512
#define DK     64
#define ND     (NROWS * DMODEL)
#define DD     (DMODEL * DMODEL)

// ---------------- scratch (device globals; allocation-free) -----------------
__device__ __half g_qkv[3][ND];         // fp16 Q/K/V projections
__device__ __half g_xh[3][ND];          // fp16 activations
__device__ __half g_wth[4][DD];         // weight^T fp16
__device__ __half g_yh[ND];             // attention output (fp16)

// ---------------- PTX helpers ----------------
static __device__ __forceinline__ uint32_t s2u(const void* p) {
    uint32_t a;
    asm("{ .reg .u64 t; cvta.to.shared.u64 t, %1; cvt.u32.u64 %0, t; }" : "=r"(a) : "l"(p));
    return a;
}
static __device__ __forceinline__ void cp16(uint32_t s, const void* g) {
    asm volatile("cp.async.cg.shared.global [%0], [%1], 16;" :: "r"(s), "l"(g));
}
static __device__ __forceinline__ void ldsm4(uint32_t& r0, uint32_t& r1, uint32_t& r2,
                                             uint32_t& r3, uint32_t a) {
    asm volatile("ldmatrix.sync.aligned.m8n8.x4.shared.b16 {%0,%1,%2,%3}, [%4];"
                 : "=r"(r0), "=r"(r1), "=r"(r2), "=r"(r3) : "r"(a));
}
static __device__ __forceinline__ void mma_f16(float* c, const uint32_t* a, const uint32_t* b) {
    asm volatile(
        "mma.sync.aligned.m16n8k16.row.col.f32.f16.f16.f32 "
        "{%0,%1,%2,%3}, {%4,%5,%6,%7}, {%8,%9}, {%0,%1,%2,%3};"
        : "+f"(c[0]), "+f"(c[1]), "+f"(c[2]), "+f"(c[3])
        : "r"(a[0]), "r"(a[1]), "r"(a[2]), "r"(a[3]), "r"(b[0]), "r"(b[1]));
}
#define SWZ(x) ((x) ^ (((x) >> 3) & 0x70))

// ---------------- GEMM: C[4096,512] = A @ B^T + bias (all fp16 ops) ----------
// Single fp16 product, fp32 accum. CTA tile 128x128, 512 threads (16 warps,
// warp tile 32x32), K chunks of 64, 3-stage cp.async pipeline.
#define KCHUNKS 8
#define STAGE_BYTES 32768     // A(16K) | B(16K), rows of 128B
#define GSMEM_TOTAL (3 * STAGE_BYTES)

struct GemmPtrs {
    const __half* A[3];
    const __half* B[3];
    const float*  bias[3];
    void*         C[3];
};

template <typename OutT>
__global__ __launch_bounds__(512, 1)
void gemm_mma_f16(GemmPtrs p)
{
    extern __shared__ char smem[];
    const uint32_t sb = s2u(smem);
    const int z = blockIdx.z;
    const __half* __restrict__ A = p.A[z];
    const __half* __restrict__ B = p.B[z];
    const float* __restrict__ bias = p.bias[z];
    OutT* __restrict__ C = (OutT*)p.C[z];

    const int tid = threadIdx.x, wid = tid >> 5, lane = tid & 31;
    const int m0 = blockIdx.y << 7, n0 = blockIdx.x << 7;
    const int wm = wid & 3, wn = wid >> 2;          // warp tile (wm*32, wn*32)

    const int a_row  = (wm << 5) + (lane & 15);                           // + mi*16
    const int a_kh   = lane >> 4;
    const int b_row0 = (wn << 5) + (((lane >> 4) & 1) << 3) + (lane & 7); // + pr*16
    const int b_kh   = (lane >> 3) & 1;

    float acc[2][4][4];
    #pragma unroll
    for (int i = 0; i < 2; i++)
        #pragma unroll
        for (int j = 0; j < 4; j++)
            #pragma unroll
            for (int r = 0; r < 4; r++) acc[i][j][r] = 0.f;

    auto load_stage = [&](int chunk, int st) {
        const uint32_t base = sb + st * STAGE_BYTES;
        const int k0 = chunk << 6;
        #pragma unroll
        for (int i = 0; i < 2; i++) {
            const int idx = (i << 9) + tid;
            const int row = idx >> 3, c = idx & 7;
            const uint32_t so = SWZ((row << 7) + (c << 4));
            const size_t aoff = (((size_t)(m0 + row) << 9) + k0 + (c << 3)) * 2;
            const size_t boff = (((size_t)(n0 + row) << 9) + k0 + (c << 3)) * 2;
            cp16(base +         so, (const char*)A + aoff);
            cp16(base + 16384 + so, (const char*)B + boff);
        }
    };

    load_stage(0, 0);
    asm volatile("cp.async.commit_group;" ::: "memory");
    load_stage(1, 1);
    asm volatile("cp.async.commit_group;" ::: "memory");

    for (int c = 0; c < KCHUNKS; c++) {
        if (c < KCHUNKS - 1)
            asm volatile("cp.async.wait_group 1;" ::: "memory");
        else
            asm volatile("cp.async.wait_group 0;" ::: "memory");
        __syncthreads();

        if (c + 2 < KCHUNKS) {
            load_stage(c + 2, (c + 2) % 3);
            asm volatile("cp.async.commit_group;" ::: "memory");
        }

        const uint32_t stb = sb + (c % 3) * STAGE_BYTES;
        #pragma unroll
        for (int t = 0; t < 4; t++) {
            uint32_t ah[2][4], bh[4][2];
            #pragma unroll
            for (int mi = 0; mi < 2; mi++) {
                const int row = a_row + (mi << 4);
                const uint32_t so = SWZ((row << 7) + (((t << 1) + a_kh) << 4));
                ldsm4(ah[mi][0], ah[mi][1], ah[mi][2], ah[mi][3], stb + so);
            }
            #pragma unroll
            for (int pr = 0; pr < 2; pr++) {
                const int row = b_row0 + (pr << 4);
                const uint32_t so = SWZ((row << 7) + (((t << 1) + b_kh) << 4));
                ldsm4(bh[2 * pr][0], bh[2 * pr][1], bh[2 * pr + 1][0], bh[2 * pr + 1][1],
                      stb + 16384 + so);
            }
            #pragma unroll
            for (int mi = 0; mi < 2; mi++)
                #pragma unroll
                for (int ni = 0; ni < 4; ni++)
                    mma_f16(acc[mi][ni], ah[mi], bh[ni]);
        }
        // top-of-loop sync at iter c+1 protects stage reuse; no trailing sync.
    }

    #pragma unroll
    for (int mi = 0; mi < 2; mi++) {
        const int row = m0 + (wm << 5) + (mi << 4) + (lane >> 2);
        #pragma unroll
        for (int ni = 0; ni < 4; ni++) {
            const int col = n0 + (wn << 5) + (ni << 3) + ((lane & 3) << 1);
            const float b0 = __ldg(bias + col), b1 = __ldg(bias + col + 1);
            if constexpr (sizeof(OutT) == 4) {
                float2 o0 = {acc[mi][ni][0] + b0, acc[mi][ni][1] + b1};
                float2 o1 = {acc[mi][ni][2] + b0, acc[mi][ni][3] + b1};
                *(float2*)((float*)C + (size_t)row * DMODEL + col)       = o0;
                *(float2*)((float*)C + (size_t)(row + 8) * DMODEL + col) = o1;
            } else {
                __half2 o0 = __floats2half2_rn(acc[mi][ni][0] + b0, acc[mi][ni][1] + b1);
                __half2 o1 = __floats2half2_rn(acc[mi][ni][2] + b0, acc[mi][ni][3] + b1);
                *(__half2*)((__half*)C + (size_t)row * DMODEL + col)       = o0;
                *(__half2*)((__half*)C + (size_t)(row + 8) * DMODEL + col) = o1;
            }
        }
    }
}

// ---------------- fused preprocessing: one launch -----------------------------
// blocks [0, 1024):  weight z = bx>>8 transpose + fp16 cvt (32x32 tiles)
// blocks [1024, 7168): activation cvt fp32->fp16
__global__ __launch_bounds__(256)
void preprocess(const float* __restrict__ w0, const float* __restrict__ w1,
                const float* __restrict__ w2, const float* __restrict__ w3,
                const float* __restrict__ x0, const float* __restrict__ x1,
                const float* __restrict__ x2,
                __half* __restrict__ Th, __half* __restrict__ H)
{
    const int bx = blockIdx.x, tid = threadIdx.x;
    if (bx < 1024) {
        __shared__ float t[32][33];
        const int z = bx >> 8, b = bx & 255;
        const float* __restrict__ W = (z == 0) ? w0 : (z == 1) ? w1 : (z == 2) ? w2 : w3;
        __half* __restrict__ th = Th + (size_t)z * DD;
        const int bxe = (b & 15) * 32, bye = (b >> 4) * 32;
        const int tx = tid & 31, ty = tid >> 5;
        const int x = bxe + tx;
        #pragma unroll
        for (int j = 0; j < 32; j += 8)
            t[ty + j][tx] = W[(size_t)(bye + ty + j) * DMODEL + x];
        __syncthreads();
        const int ox = bye + tx;
        #pragma unroll
        for (int j = 0; j < 32; j += 8)
            th[(size_t)(bxe + ty + j) * DMODEL + ox] = __float2half(t[tx][ty + j]);
    } else {
        const int idx = bx - 1024;
        const int z = idx >> 11;
        const int blk = idx & 2047;
        const float* __restrict__ X = (z == 0) ? x0 : (z == 1) ? x1 : x2;
        const int i = (blk * 256 + tid) << 2;
        const float4 v = *(const float4*)(X + i);
        __half2 p0 = __floats2half2_rn(v.x, v.y);
        __half2 p1 = __floats2half2_rn(v.z, v.w);
        uint2 o = {*(uint32_t*)&p0, *(uint32_t*)&p1};
        *(uint2*)(H + (size_t)z * ND + i) = o;
    }
}

// ---------------- fused attention + residual (fp16 in, fp16 out) ------------
__global__ __launch_bounds__(256, 8)
void attn_residual_h(const __half* __restrict__ q, const __half* __restrict__ k,
                     const __half* __restrict__ v, const float* __restrict__ xq,
                     __half* __restrict__ yh)
{
    __shared__ __half2 sk2[8][DK];
    __shared__ __half2 sv2[8][DK];
    const int warp = threadIdx.x >> 5;
    const int lane = threadIdx.x & 31;
    const int gw   = blockIdx.x * 8 + warp;
    const int base = (gw >> 3) * DMODEL + (gw & 7) * DK;

    sk2[warp][lane]      = __half2half2(k[base + lane]);
    sk2[warp][lane + 32] = __half2half2(k[base + lane + 32]);
    sv2[warp][lane]      = __half2half2(v[base + lane]);
    sv2[warp][lane + 32] = __half2half2(v[base + lane + 32]);
    const float SCL = 0.125f * 1.4426950408889634f;   // 1/sqrt(dk) * log2(e)
    const __half2 a01 = __floats2half2_rn(__half2float(q[base + lane]) * SCL,
                                          __half2float(q[base + lane + 32]) * SCL);
    __syncwarp();

    // chunked fp16x2 accumulation: flush partials to fp32 every 16 j's
    float num0 = 0.f, num1 = 0.f, den0 = 0.f, den1 = 0.f;
    #pragma unroll
    for (int jc = 0; jc < 4; jc++) {
        __half2 np = __float2half2_rn(0.f);
        __half2 dp = __float2half2_rn(0.f);
        #pragma unroll
        for (int j16 = 0; j16 < 16; j16++) {
            const int j = (jc << 4) + j16;
            const __half2 e = h2exp2(__hmul2(a01, sk2[warp][j]));
            np = __hfma2(e, sv2[warp][j], np);
            dp = __hadd2(dp, e);
        }
        const float2 nf = __half22float2(np);
        const float2 df = __half22float2(dp);
        num0 += nf.x; num1 += nf.y;
        den0 += df.x; den1 += df.y;
    }
    const float y0 = xq[base + lane]      - __fdividef(num0, den0);
    const float y1 = xq[base + lane + 32] - __fdividef(num1, den1);
    yh[base + lane]      = __float2half(y0);
    yh[base + lane + 32] = __float2half(y1);
}

// ---------------- launch ------------------------------------------------------
extern "C" void kernel_launch(void* const* d_in, const int* in_sizes, int n_in,
                              void* d_out, int out_size)
{
    const float* x_q = (const float*)d_in[0];
    const float* x_k = (const float*)d_in[1];
    const float* x_v = (const float*)d_in[2];
    const float* Wq = (const float*)d_in[3];
    const float* bq = (const float*)d_in[4];
    const float* Wk = (const float*)d_in[5];
    const float* bk = (const float*)d_in[6];
    const float* Wv = (const float*)d_in[7];
    const float* bv = (const float*)d_in[8];
    const float* Wo = (const float*)d_in[9];
    const float* bo = (const float*)d_in[10];
    float* out = (float*)d_out;

    cudaFuncSetAttribute(gemm_mma_f16<__half>, cudaFuncAttributeMaxDynamicSharedMemorySize,
                         GSMEM_TOTAL);
    cudaFuncSetAttribute(gemm_mma_f16<float>, cudaFuncAttributeMaxDynamicSharedMemorySize,
                         GSMEM_TOTAL);

    __half *qkv, *xh, *wth, *yh;
    cudaGetSymbolAddress((void**)&qkv, g_qkv);
    cudaGetSymbolAddress((void**)&xh, g_xh);
    cudaGetSymbolAddress((void**)&wth, g_wth);
    cudaGetSymbolAddress((void**)&yh, g_yh);

    // 1) all preprocessing in one launch (4 weight transposes + 3 cvt)
    preprocess<<<1024 + 3 * (ND / 1024), 256>>>(Wq, Wk, Wv, Wo, x_q, x_k, x_v, wth, xh);

    // 2) Q/K/V projection GEMMs in one launch (grid.z = 3), fp16 outputs
    GemmPtrs pq;
    for (int z = 0; z < 3; z++) {
        pq.A[z] = xh + (size_t)z * ND;
        pq.B[z] = wth + (size_t)z * DD;
        pq.C[z] = qkv + (size_t)z * ND;
    }
    pq.bias[0] = bq; pq.bias[1] = bk; pq.bias[2] = bv;
    gemm_mma_f16<__half><<<dim3(4, 32, 3), 512, GSMEM_TOTAL>>>(pq);

    // 3) attention + residual (fp16 in/out)
    attn_residual_h<<<NROWS, 256>>>(qkv, qkv + ND, qkv + 2 * (size_t)ND, x_q, yh);

    // 4) output projection, fp32 output
    GemmPtrs po;
    po.A[0] = yh;
    po.B[0] = wth + (size_t)3 * DD;
    po.bias[0] = bo;
    po.C[0] = out;
    po.A[1] = po.A[2] = po.A[0];
    po.B[1] = po.B[2] = po.B[0];
    po.bias[1] = po.bias[2] = bo;
    po.C[1] = po.C[2] = po.C[0];
    gemm_mma_f16<float><<<dim3(4, 32, 1), 512, GSMEM_TOTAL>>>(po);
}

// round 8
// speedup vs baseline: 4.4702x; 1.0327x over previous
#include <cuda_runtime.h>
#include <cuda_fp16.h>
#include <cstdint>

#define NROWS  4096
#define DMODEL 512
#define DK     64
#define ND     (NROWS * DMODEL)
#define DD     (DMODEL * DMODEL)

// ---------------- scratch (device globals; allocation-free) -----------------
__device__ __half g_qkv[3][ND];         // fp16 Q/K/V projections
__device__ __half g_xh[3][ND];          // fp16 activations
__device__ __half g_wth[4][DD];         // weight^T fp16
__device__ __half g_yh[ND];             // attention output (fp16)

// ---------------- PTX helpers ----------------
static __device__ __forceinline__ uint32_t s2u(const void* p) {
    uint32_t a;
    asm("{ .reg .u64 t; cvta.to.shared.u64 t, %1; cvt.u32.u64 %0, t; }" : "=r"(a) : "l"(p));
    return a;
}
static __device__ __forceinline__ void cp16(uint32_t s, const void* g) {
    asm volatile("cp.async.cg.shared.global [%0], [%1], 16;" :: "r"(s), "l"(g));
}
static __device__ __forceinline__ void ldsm4(uint32_t& r0, uint32_t& r1, uint32_t& r2,
                                             uint32_t& r3, uint32_t a) {
    asm volatile("ldmatrix.sync.aligned.m8n8.x4.shared.b16 {%0,%1,%2,%3}, [%4];"
                 : "=r"(r0), "=r"(r1), "=r"(r2), "=r"(r3) : "r"(a));
}
static __device__ __forceinline__ void mma_f16(float* c, const uint32_t* a, const uint32_t* b) {
    asm volatile(
        "mma.sync.aligned.m16n8k16.row.col.f32.f16.f16.f32 "
        "{%0,%1,%2,%3}, {%4,%5,%6,%7}, {%8,%9}, {%0,%1,%2,%3};"
        : "+f"(c[0]), "+f"(c[1]), "+f"(c[2]), "+f"(c[3])
        : "r"(a[0]), "r"(a[1]), "r"(a[2]), "r"(a[3]), "r"(b[0]), "r"(b[1]));
}
#define SWZ(x) ((x) ^ (((x) >> 3) & 0x70))

// ---------------- GEMM: C[4096,512] = A @ B^T + bias (fp16, fp32 accum) ------
// CTA tile 128x64, 256 threads (8 warps: 4m x 2n, warp tile 32x32).
// K chunks of 64, 4-stage cp.async pipeline (24KB/stage, 96KB total) ->
// 2 CTAs co-resident per SM for cross-CTA latency hiding.
#define KCHUNKS 8
#define NSTAGE  4
#define STAGE_BYTES 24576     // A(16K) | B(8K), rows of 128B
#define GSMEM_TOTAL (NSTAGE * STAGE_BYTES)

struct GemmPtrs {
    const __half* A[3];
    const __half* B[3];
    const float*  bias[3];
    void*         C[3];
};

template <typename OutT>
__global__ __launch_bounds__(256, 2)
void gemm_mma_f16(GemmPtrs p)
{
    extern __shared__ char smem[];
    const uint32_t sb = s2u(smem);
    const int z = blockIdx.z;
    const __half* __restrict__ A = p.A[z];
    const __half* __restrict__ B = p.B[z];
    const float* __restrict__ bias = p.bias[z];
    OutT* __restrict__ C = (OutT*)p.C[z];

    const int tid = threadIdx.x, wid = tid >> 5, lane = tid & 31;
    const int m0 = blockIdx.y << 7, n0 = blockIdx.x << 6;
    const int wm = wid & 3, wn = wid >> 2;          // warp tile (wm*32, wn*32)

    const int a_row  = (wm << 5) + (lane & 15);                           // + mi*16
    const int a_kh   = lane >> 4;
    const int b_row0 = (wn << 5) + (((lane >> 4) & 1) << 3) + (lane & 7); // + pr*16
    const int b_kh   = (lane >> 3) & 1;

    float acc[2][4][4];
    #pragma unroll
    for (int i = 0; i < 2; i++)
        #pragma unroll
        for (int j = 0; j < 4; j++)
            #pragma unroll
            for (int r = 0; r < 4; r++) acc[i][j][r] = 0.f;

    auto load_stage = [&](int chunk, int st) {
        const uint32_t base = sb + st * STAGE_BYTES;
        const int k0 = chunk << 6;
        // A tile: 128 rows x 128B = 1024 cp16 -> 4 per thread
        #pragma unroll
        for (int i = 0; i < 4; i++) {
            const int idx = (i << 8) + tid;
            const int row = idx >> 3, c = idx & 7;
            const uint32_t so = SWZ((row << 7) + (c << 4));
            const size_t aoff = (((size_t)(m0 + row) << 9) + k0 + (c << 3)) * 2;
            cp16(base + so, (const char*)A + aoff);
        }
        // B tile: 64 rows x 128B = 512 cp16 -> 2 per thread
        #pragma unroll
        for (int i = 0; i < 2; i++) {
            const int idx = (i << 8) + tid;
            const int row = idx >> 3, c = idx & 7;
            const uint32_t so = SWZ((row << 7) + (c << 4));
            const size_t boff = (((size_t)(n0 + row) << 9) + k0 + (c << 3)) * 2;
            cp16(base + 16384 + so, (const char*)B + boff);
        }
    };

    load_stage(0, 0);
    asm volatile("cp.async.commit_group;" ::: "memory");
    load_stage(1, 1);
    asm volatile("cp.async.commit_group;" ::: "memory");
    load_stage(2, 2);
    asm volatile("cp.async.commit_group;" ::: "memory");

    #pragma unroll
    for (int c = 0; c < KCHUNKS; c++) {
        // ensure chunk c has arrived: pending <= min(2, 7-c)
        const int pend = (7 - c) < 2 ? (7 - c) : 2;
        if (pend == 2)      asm volatile("cp.async.wait_group 2;" ::: "memory");
        else if (pend == 1) asm volatile("cp.async.wait_group 1;" ::: "memory");
        else                asm volatile("cp.async.wait_group 0;" ::: "memory");
        __syncthreads();

        if (c + 3 < KCHUNKS) {
            load_stage(c + 3, (c + 3) & 3);
            asm volatile("cp.async.commit_group;" ::: "memory");
        }

        const uint32_t stb = sb + (c & 3) * STAGE_BYTES;
        #pragma unroll
        for (int t = 0; t < 4; t++) {
            uint32_t ah[2][4], bh[4][2];
            #pragma unroll
            for (int mi = 0; mi < 2; mi++) {
                const int row = a_row + (mi << 4);
                const uint32_t so = SWZ((row << 7) + (((t << 1) + a_kh) << 4));
                ldsm4(ah[mi][0], ah[mi][1], ah[mi][2], ah[mi][3], stb + so);
            }
            #pragma unroll
            for (int pr = 0; pr < 2; pr++) {
                const int row = b_row0 + (pr << 4);
                const uint32_t so = SWZ((row << 7) + (((t << 1) + b_kh) << 4));
                ldsm4(bh[2 * pr][0], bh[2 * pr][1], bh[2 * pr + 1][0], bh[2 * pr + 1][1],
                      stb + 16384 + so);
            }
            #pragma unroll
            for (int mi = 0; mi < 2; mi++)
                #pragma unroll
                for (int ni = 0; ni < 4; ni++)
                    mma_f16(acc[mi][ni], ah[mi], bh[ni]);
        }
        // top-of-loop sync at iter c+1 protects stage reuse; no trailing sync.
    }

    #pragma unroll
    for (int mi = 0; mi < 2; mi++) {
        const int row = m0 + (wm << 5) + (mi << 4) + (lane >> 2);
        #pragma unroll
        for (int ni = 0; ni < 4; ni++) {
            const int col = n0 + (wn << 5) + (ni << 3) + ((lane & 3) << 1);
            const float b0 = __ldg(bias + col), b1 = __ldg(bias + col + 1);
            if constexpr (sizeof(OutT) == 4) {
                float2 o0 = {acc[mi][ni][0] + b0, acc[mi][ni][1] + b1};
                float2 o1 = {acc[mi][ni][2] + b0, acc[mi][ni][3] + b1};
                *(float2*)((float*)C + (size_t)row * DMODEL + col)       = o0;
                *(float2*)((float*)C + (size_t)(row + 8) * DMODEL + col) = o1;
            } else {
                __half2 o0 = __floats2half2_rn(acc[mi][ni][0] + b0, acc[mi][ni][1] + b1);
                __half2 o1 = __floats2half2_rn(acc[mi][ni][2] + b0, acc[mi][ni][3] + b1);
                *(__half2*)((__half*)C + (size_t)row * DMODEL + col)       = o0;
                *(__half2*)((__half*)C + (size_t)(row + 8) * DMODEL + col) = o1;
            }
        }
    }
}

// ---------------- fused preprocessing: one launch -----------------------------
__global__ __launch_bounds__(256)
void preprocess(const float* __restrict__ w0, const float* __restrict__ w1,
                const float* __restrict__ w2, const float* __restrict__ w3,
                const float* __restrict__ x0, const float* __restrict__ x1,
                const float* __restrict__ x2,
                __half* __restrict__ Th, __half* __restrict__ H)
{
    const int bx = blockIdx.x, tid = threadIdx.x;
    if (bx < 1024) {
        __shared__ float t[32][33];
        const int z = bx >> 8, b = bx & 255;
        const float* __restrict__ W = (z == 0) ? w0 : (z == 1) ? w1 : (z == 2) ? w2 : w3;
        __half* __restrict__ th = Th + (size_t)z * DD;
        const int bxe = (b & 15) * 32, bye = (b >> 4) * 32;
        const int tx = tid & 31, ty = tid >> 5;
        const int x = bxe + tx;
        #pragma unroll
        for (int j = 0; j < 32; j += 8)
            t[ty + j][tx] = W[(size_t)(bye + ty + j) * DMODEL + x];
        __syncthreads();
        const int ox = bye + tx;
        #pragma unroll
        for (int j = 0; j < 32; j += 8)
            th[(size_t)(bxe + ty + j) * DMODEL + ox] = __float2half(t[tx][ty + j]);
    } else {
        const int idx = bx - 1024;
        const int z = idx >> 11;
        const int blk = idx & 2047;
        const float* __restrict__ X = (z == 0) ? x0 : (z == 1) ? x1 : x2;
        const int i = (blk * 256 + tid) << 2;
        const float4 v = *(const float4*)(X + i);
        __half2 p0 = __floats2half2_rn(v.x, v.y);
        __half2 p1 = __floats2half2_rn(v.z, v.w);
        uint2 o = {*(uint32_t*)&p0, *(uint32_t*)&p1};
        *(uint2*)(H + (size_t)z * ND + i) = o;
    }
}

// ---------------- fused attention + residual (fp16 in, fp16 out) ------------
__global__ __launch_bounds__(256, 8)
void attn_residual_h(const __half* __restrict__ q, const __half* __restrict__ k,
                     const __half* __restrict__ v, const float* __restrict__ xq,
                     __half* __restrict__ yh)
{
    __shared__ __half2 sk2[8][DK];
    __shared__ __half2 sv2[8][DK];
    const int warp = threadIdx.x >> 5;
    const int lane = threadIdx.x & 31;
    const int gw   = blockIdx.x * 8 + warp;
    const int base = (gw >> 3) * DMODEL + (gw & 7) * DK;

    sk2[warp][lane]      = __half2half2(k[base + lane]);
    sk2[warp][lane + 32] = __half2half2(k[base + lane + 32]);
    sv2[warp][lane]      = __half2half2(v[base + lane]);
    sv2[warp][lane + 32] = __half2half2(v[base + lane + 32]);
    const float SCL = 0.125f * 1.4426950408889634f;   // 1/sqrt(dk) * log2(e)
    const __half2 a01 = __floats2half2_rn(__half2float(q[base + lane]) * SCL,
                                          __half2float(q[base + lane + 32]) * SCL);
    __syncwarp();

    float num0 = 0.f, num1 = 0.f, den0 = 0.f, den1 = 0.f;
    #pragma unroll
    for (int jc = 0; jc < 4; jc++) {
        __half2 np = __float2half2_rn(0.f);
        __half2 dp = __float2half2_rn(0.f);
        #pragma unroll
        for (int j16 = 0; j16 < 16; j16++) {
            const int j = (jc << 4) + j16;
            const __half2 e = h2exp2(__hmul2(a01, sk2[warp][j]));
            np = __hfma2(e, sv2[warp][j], np);
            dp = __hadd2(dp, e);
        }
        const float2 nf = __half22float2(np);
        const float2 df = __half22float2(dp);
        num0 += nf.x; num1 += nf.y;
        den0 += df.x; den1 += df.y;
    }
    const float y0 = xq[base + lane]      - __fdividef(num0, den0);
    const float y1 = xq[base + lane + 32] - __fdividef(num1, den1);
    yh[base + lane]      = __float2half(y0);
    yh[base + lane + 32] = __float2half(y1);
}

// ---------------- launch ------------------------------------------------------
extern "C" void kernel_launch(void* const* d_in, const int* in_sizes, int n_in,
                              void* d_out, int out_size)
{
    const float* x_q = (const float*)d_in[0];
    const float* x_k = (const float*)d_in[1];
    const float* x_v = (const float*)d_in[2];
    const float* Wq = (const float*)d_in[3];
    const float* bq = (const float*)d_in[4];
    const float* Wk = (const float*)d_in[5];
    const float* bk = (const float*)d_in[6];
    const float* Wv = (const float*)d_in[7];
    const float* bv = (const float*)d_in[8];
    const float* Wo = (const float*)d_in[9];
    const float* bo = (const float*)d_in[10];
    float* out = (float*)d_out;

    cudaFuncSetAttribute(gemm_mma_f16<__half>, cudaFuncAttributeMaxDynamicSharedMemorySize,
                         GSMEM_TOTAL);
    cudaFuncSetAttribute(gemm_mma_f16<float>, cudaFuncAttributeMaxDynamicSharedMemorySize,
                         GSMEM_TOTAL);

    __half *qkv, *xh, *wth, *yh;
    cudaGetSymbolAddress((void**)&qkv, g_qkv);
    cudaGetSymbolAddress((void**)&xh, g_xh);
    cudaGetSymbolAddress((void**)&wth, g_wth);
    cudaGetSymbolAddress((void**)&yh, g_yh);

    // 1) all preprocessing in one launch (4 weight transposes + 3 cvt)
    preprocess<<<1024 + 3 * (ND / 1024), 256>>>(Wq, Wk, Wv, Wo, x_q, x_k, x_v, wth, xh);

    // 2) Q/K/V projection GEMMs in one launch (grid.z = 3), fp16 outputs
    GemmPtrs pq;
    for (int z = 0; z < 3; z++) {
        pq.A[z] = xh + (size_t)z * ND;
        pq.B[z] = wth + (size_t)z * DD;
        pq.C[z] = qkv + (size_t)z * ND;
    }
    pq.bias[0] = bq; pq.bias[1] = bk; pq.bias[2] = bv;
    gemm_mma_f16<__half><<<dim3(8, 32, 3), 256, GSMEM_TOTAL>>>(pq);

    // 3) attention + residual (fp16 in/out)
    attn_residual_h<<<NROWS, 256>>>(qkv, qkv + ND, qkv + 2 * (size_t)ND, x_q, yh);

    // 4) output projection, fp32 output
    GemmPtrs po;
    po.A[0] = yh;
    po.B[0] = wth + (size_t)3 * DD;
    po.bias[0] = bo;
    po.C[0] = out;
    po.A[1] = po.A[2] = po.A[0];
    po.B[1] = po.B[2] = po.B[0];
    po.bias[1] = po.bias[2] = bo;
    po.C[1] = po.C[2] = po.C[0];
    gemm_mma_f16<float><<<dim3(8, 32, 1), 256, GSMEM_TOTAL>>>(po);
}